// round 7
// baseline (speedup 1.0000x reference)
#include <cuda_runtime.h>
#include <math.h>
#include <stdint.h>

// Problem constants (fixed for this problem instance)
#define NMAX   50000
#define EMAX   800000
#define F_IN   512
#define H1     256
#define H2     16
#define F_OUT  40

#define SCAN_B 256

// Scratch (static device arrays; no allocation allowed)
__device__ float g_p1[NMAX * H1];   // dinv ⊙ (x @ W1)
__device__ float g_p2[NMAX * H2];   // dinv ⊙ (relu(Ahat h1 + b1) @ W2)
__device__ float g_p3[NMAX * H2];   // dinv ⊙ relu(Ahat h2 + b2)
__device__ float g_a3[NMAX * H2];   // Ahat r2
__device__ int   g_deg[NMAX];       // edge-only in-degree (no self loop)
__device__ int   g_rowstart[NMAX];
__device__ int   g_cursor[NMAX];
__device__ int   g_csrc[EMAX];      // src indices grouped by dst (CSR)
__device__ int   g_bsum[SCAN_B];
__device__ float g_dinv[NMAX];

// ---------------------------------------------------------------------------
// degree / scan / CSR fill / dinv
// ---------------------------------------------------------------------------
__global__ void zero_deg_kernel(int N) {
    int i = blockIdx.x * blockDim.x + threadIdx.x;
    if (i < N) g_deg[i] = 0;
}

__global__ void count_deg_kernel(const int* __restrict__ ei, int E, int N) {
    int e = blockIdx.x * blockDim.x + threadIdx.x;
    if (e < E) {
        int d = ei[E + e];
        if ((unsigned)d < (unsigned)N) atomicAdd(&g_deg[d], 1);
    }
}

__global__ void scan_partial_kernel(int N) {
    __shared__ int sd[SCAN_B];
    int t = threadIdx.x, b = blockIdx.x;
    int i = b * SCAN_B + t;
    int v = (i < N) ? g_deg[i] : 0;
    sd[t] = v;
    __syncthreads();
#pragma unroll
    for (int off = 1; off < SCAN_B; off <<= 1) {
        int x = (t >= off) ? sd[t - off] : 0;
        __syncthreads();
        sd[t] += x;
        __syncthreads();
    }
    if (i < N) g_rowstart[i] = sd[t] - v;       // exclusive
    if (t == SCAN_B - 1) g_bsum[b] = sd[t];
}

__global__ void scan_bsum_kernel(int nblk) {
    __shared__ int sd[SCAN_B];
    int t = threadIdx.x;
    int v = (t < nblk) ? g_bsum[t] : 0;
    sd[t] = v;
    __syncthreads();
#pragma unroll
    for (int off = 1; off < SCAN_B; off <<= 1) {
        int x = (t >= off) ? sd[t - off] : 0;
        __syncthreads();
        sd[t] += x;
        __syncthreads();
    }
    if (t < nblk) g_bsum[t] = sd[t] - v;
}

// merged: finalize rowstart, init cursor, compute dinv
__global__ void scan_add_dinv_kernel(int N) {
    int i = blockIdx.x * blockDim.x + threadIdx.x;
    if (i < N) {
        int r = g_rowstart[i] + g_bsum[i / SCAN_B];
        g_rowstart[i] = r;
        g_cursor[i] = r;
        g_dinv[i] = rsqrtf((float)(g_deg[i] + 1));   // +1 self-loop
    }
}

__global__ void csr_fill_kernel(const int* __restrict__ ei, int E, int N) {
    int e = blockIdx.x * blockDim.x + threadIdx.x;
    if (e < E) {
        int s = ei[e];
        int d = ei[E + e];
        if ((unsigned)s < (unsigned)N && (unsigned)d < (unsigned)N) {
            int pos = atomicAdd(&g_cursor[d], 1);
            g_csrc[pos] = s;
        }
    }
}

// ---------------------------------------------------------------------------
// GEMM1 (tf32 tensor cores): g_p1[N,256] = dinv ⊙ (A[N,512] @ B[512,256])
// block 128x128x16, 8 warps, warp tile 64x32 via mma.m16n8k8.tf32
// ---------------------------------------------------------------------------
#define G1_BM 128
#define G1_BN 128
#define G1_BK 16
#define AS_STRIDE 20
#define BS_STRIDE 132

__device__ __forceinline__ uint32_t f2tf32(float x) {
    uint32_t r;
    asm("cvt.rna.tf32.f32 %0, %1;" : "=r"(r) : "f"(x));
    return r;
}

__device__ __forceinline__ void mma_tf32(float c[4], const uint32_t a[4],
                                         const uint32_t b[2]) {
    asm volatile(
        "mma.sync.aligned.m16n8k8.row.col.f32.tf32.tf32.f32 "
        "{%0,%1,%2,%3}, {%4,%5,%6,%7}, {%8,%9}, {%0,%1,%2,%3};"
        : "+f"(c[0]), "+f"(c[1]), "+f"(c[2]), "+f"(c[3])
        : "r"(a[0]), "r"(a[1]), "r"(a[2]), "r"(a[3]), "r"(b[0]), "r"(b[1]));
}

__global__ void __launch_bounds__(256) gemm1_kernel(const float* __restrict__ A,
                                                    const float* __restrict__ B,
                                                    int N) {
    const int K = F_IN, M = H1;
    __shared__ uint32_t As[2][G1_BM * AS_STRIDE];
    __shared__ uint32_t Bs[2][G1_BK * BS_STRIDE];

    int tid = threadIdx.x;
    int lane = tid & 31;
    int w = tid >> 5;
    int wm = w >> 2;
    int wn = w & 3;
    int brow = blockIdx.y * G1_BM;
    int bcol = blockIdx.x * G1_BN;

    int arow = tid >> 1;
    int acg  = (tid & 1) * 4;
    int bk   = tid >> 4;
    int bn   = (tid & 15) * 4;

    float acc[4][4][4];
#pragma unroll
    for (int mi = 0; mi < 4; mi++)
#pragma unroll
        for (int ni = 0; ni < 4; ni++)
#pragma unroll
            for (int q = 0; q < 4; q++) acc[mi][ni][q] = 0.f;

    float4 a4a, a4b, b4a, b4b;
    {
        int gr = brow + arow;
        if (gr < N) {
            a4a = *(const float4*)&A[(long)gr * K + acg];
            a4b = *(const float4*)&A[(long)gr * K + acg + 8];
        } else {
            a4a = make_float4(0.f, 0.f, 0.f, 0.f);
            a4b = a4a;
        }
        b4a = *(const float4*)&B[(long)bk * M + bcol + bn];
        b4b = *(const float4*)&B[(long)bk * M + bcol + bn + 64];
    }
    {
        uint32_t* ap = &As[0][arow * AS_STRIDE + acg];
        ap[0] = f2tf32(a4a.x); ap[1] = f2tf32(a4a.y);
        ap[2] = f2tf32(a4a.z); ap[3] = f2tf32(a4a.w);
        ap[8] = f2tf32(a4b.x); ap[9] = f2tf32(a4b.y);
        ap[10] = f2tf32(a4b.z); ap[11] = f2tf32(a4b.w);
        uint32_t* bp = &Bs[0][bk * BS_STRIDE + bn];
        bp[0] = f2tf32(b4a.x); bp[1] = f2tf32(b4a.y);
        bp[2] = f2tf32(b4a.z); bp[3] = f2tf32(b4a.w);
        bp[64] = f2tf32(b4b.x); bp[65] = f2tf32(b4b.y);
        bp[66] = f2tf32(b4b.z); bp[67] = f2tf32(b4b.w);
    }
    __syncthreads();

    int buf = 0;
    for (int k0 = 0; k0 < K; k0 += G1_BK) {
        int knext = k0 + G1_BK;
        if (knext < K) {
            int gr = brow + arow;
            if (gr < N) {
                a4a = *(const float4*)&A[(long)gr * K + knext + acg];
                a4b = *(const float4*)&A[(long)gr * K + knext + acg + 8];
            } else {
                a4a = make_float4(0.f, 0.f, 0.f, 0.f);
                a4b = a4a;
            }
            b4a = *(const float4*)&B[(long)(knext + bk) * M + bcol + bn];
            b4b = *(const float4*)&B[(long)(knext + bk) * M + bcol + bn + 64];
        }

#pragma unroll
        for (int ks = 0; ks < 2; ks++) {
            int kk = ks * 8;
            uint32_t af[4][4], bf[4][2];
#pragma unroll
            for (int mi = 0; mi < 4; mi++) {
                int r = wm * 64 + mi * 16 + (lane >> 2);
                int c = kk + (lane & 3);
                af[mi][0] = As[buf][r * AS_STRIDE + c];
                af[mi][1] = As[buf][(r + 8) * AS_STRIDE + c];
                af[mi][2] = As[buf][r * AS_STRIDE + c + 4];
                af[mi][3] = As[buf][(r + 8) * AS_STRIDE + c + 4];
            }
#pragma unroll
            for (int ni = 0; ni < 4; ni++) {
                int c = wn * 32 + ni * 8 + (lane >> 2);
                int k1 = kk + (lane & 3);
                bf[ni][0] = Bs[buf][k1 * BS_STRIDE + c];
                bf[ni][1] = Bs[buf][(k1 + 4) * BS_STRIDE + c];
            }
#pragma unroll
            for (int mi = 0; mi < 4; mi++)
#pragma unroll
                for (int ni = 0; ni < 4; ni++)
                    mma_tf32(acc[mi][ni], af[mi], bf[ni]);
        }

        if (knext < K) {
            int nb = buf ^ 1;
            uint32_t* ap = &As[nb][arow * AS_STRIDE + acg];
            ap[0] = f2tf32(a4a.x); ap[1] = f2tf32(a4a.y);
            ap[2] = f2tf32(a4a.z); ap[3] = f2tf32(a4a.w);
            ap[8] = f2tf32(a4b.x); ap[9] = f2tf32(a4b.y);
            ap[10] = f2tf32(a4b.z); ap[11] = f2tf32(a4b.w);
            uint32_t* bp = &Bs[nb][bk * BS_STRIDE + bn];
            bp[0] = f2tf32(b4a.x); bp[1] = f2tf32(b4a.y);
            bp[2] = f2tf32(b4a.z); bp[3] = f2tf32(b4a.w);
            bp[64] = f2tf32(b4b.x); bp[65] = f2tf32(b4b.y);
            bp[66] = f2tf32(b4b.z); bp[67] = f2tf32(b4b.w);
            __syncthreads();
            buf = nb;
        }
    }

#pragma unroll
    for (int mi = 0; mi < 4; mi++) {
        int r0 = brow + wm * 64 + mi * 16 + (lane >> 2);
        int r1 = r0 + 8;
        float dv0 = (r0 < N) ? g_dinv[r0] : 0.f;
        float dv1 = (r1 < N) ? g_dinv[r1] : 0.f;
#pragma unroll
        for (int ni = 0; ni < 4; ni++) {
            int c = bcol + wn * 32 + ni * 8 + (lane & 3) * 2;
            if (r0 < N) {
                float2 v = make_float2(dv0 * acc[mi][ni][0], dv0 * acc[mi][ni][1]);
                *(float2*)&g_p1[(long)r0 * M + c] = v;
            }
            if (r1 < N) {
                float2 v = make_float2(dv1 * acc[mi][ni][2], dv1 * acc[mi][ni][3]);
                *(float2*)&g_p1[(long)r1 * M + c] = v;
            }
        }
    }
}

// ---------------------------------------------------------------------------
// layer2_fused: for 16 nodes per block —
//   row[d] = relu(dinv[d]*(p1[d] + sum_nbr p1[s]) + b1)       (gather, smem)
//   p2[d]  = dinv[d] * (row[d] @ W2)                          (smem GEMM)
// Eliminates the g_a1 round trip entirely.
// ---------------------------------------------------------------------------
__global__ void __launch_bounds__(256) layer2_fused_kernel(
    const float* __restrict__ b1, const float* __restrict__ W2, int N) {
    __shared__ float Ws[H1 * H2];        // 16 KB
    __shared__ float rows[16][H1 + 1];   // 16 x 257 floats ≈ 16.1 KB
    __shared__ int nbr[256];

    int tid = threadIdx.x;
    for (int i = tid; i < H1 * H2; i += 256) Ws[i] = W2[i];

    int node0 = blockIdx.x * 16;
    float bias = b1[tid];               // tid == feature index f

    int nlocal = min(16, N - node0);
    for (int r = 0; r < nlocal; r++) {
        int d = node0 + r;
        int start = g_rowstart[d];
        int deg = g_deg[d];

        float acc0 = g_p1[(long)d * H1 + tid];   // self loop (p1 pre-scaled)
        float acc1 = 0.f;
        for (int base = 0; base < deg; base += 256) {
            int cnt = min(256, deg - base);
            if (tid < cnt) nbr[tid] = g_csrc[start + base + tid];
            __syncthreads();
            int j = 0;
            for (; j + 1 < cnt; j += 2) {
                acc0 += g_p1[(long)nbr[j] * H1 + tid];
                acc1 += g_p1[(long)nbr[j + 1] * H1 + tid];
            }
            if (j < cnt) acc0 += g_p1[(long)nbr[j] * H1 + tid];
            __syncthreads();
        }
        float v = g_dinv[d] * (acc0 + acc1) + bias;
        rows[r][tid] = v > 0.f ? v : 0.f;
    }
    __syncthreads();

    // phase B: 16x16 thread grid, dot with W2 from smem
    int ty = tid >> 4;   // local row (node)
    int tx = tid & 15;   // out col
    int n = node0 + ty;
    if (ty < nlocal && n < N) {
        float acc = 0.f;
#pragma unroll 8
        for (int k = 0; k < H1; k++) acc += rows[ty][k] * Ws[k * H2 + tx];
        g_p2[(long)n * H2 + tx] = g_dinv[n] * acc;
    }
}

// ---------------------------------------------------------------------------
// gather2 (F=16): p3[d] = dinv[d] * relu(dinv[d]*(p2[d]+sum p2[s]) + b2)
// ---------------------------------------------------------------------------
__global__ void __launch_bounds__(256) gather2_kernel(const float* __restrict__ b2, int N) {
    int t = threadIdx.x;
    int d = blockIdx.x * 16 + (t >> 4);
    int f = t & 15;
    if (d >= N) return;

    int start = g_rowstart[d];
    int deg = g_deg[d];
    float acc0 = g_p2[(long)d * H2 + f];
    float acc1 = 0.f;
    int j = 0;
    for (; j + 1 < deg; j += 2) {
        int s0 = g_csrc[start + j];
        int s1 = g_csrc[start + j + 1];
        acc0 += g_p2[(long)s0 * H2 + f];
        acc1 += g_p2[(long)s1 * H2 + f];
    }
    if (j < deg) acc0 += g_p2[(long)g_csrc[start + j] * H2 + f];

    float dv = g_dinv[d];
    float v = dv * (acc0 + acc1) + b2[f];
    g_p3[(long)d * H2 + f] = dv * (v > 0.f ? v : 0.f);
}

// ---------------------------------------------------------------------------
// gather3 (F=16): a3[d] = dinv[d]*(p3[d]+sum p3[s])
// ---------------------------------------------------------------------------
__global__ void __launch_bounds__(256) gather3_kernel(int N) {
    int t = threadIdx.x;
    int d = blockIdx.x * 16 + (t >> 4);
    int f = t & 15;
    if (d >= N) return;

    int start = g_rowstart[d];
    int deg = g_deg[d];
    float acc0 = g_p3[(long)d * H2 + f];
    float acc1 = 0.f;
    int j = 0;
    for (; j + 1 < deg; j += 2) {
        int s0 = g_csrc[start + j];
        int s1 = g_csrc[start + j + 1];
        acc0 += g_p3[(long)s0 * H2 + f];
        acc1 += g_p3[(long)s1 * H2 + f];
    }
    if (j < deg) acc0 += g_p3[(long)g_csrc[start + j] * H2 + f];

    g_a3[(long)d * H2 + f] = g_dinv[d] * (acc0 + acc1);
}

// ---------------------------------------------------------------------------
// final: o = g_a3 @ W3 + b3 ; log_softmax ; one thread per node
// ---------------------------------------------------------------------------
__global__ void final_kernel(const float* __restrict__ W3,
                             const float* __restrict__ b3,
                             float* __restrict__ out, int N) {
    __shared__ float Ws[H2 * F_OUT];
    __shared__ float bs[F_OUT];
    int tid = threadIdx.x;
    for (int i = tid; i < H2 * F_OUT; i += blockDim.x) Ws[i] = W3[i];
    if (tid < F_OUT) bs[tid] = b3[tid];
    __syncthreads();

    int n = blockIdx.x * blockDim.x + tid;
    if (n >= N) return;

    float a[H2];
    const float4* ap = (const float4*)(g_a3 + (long)n * H2);
#pragma unroll
    for (int i = 0; i < 4; i++) {
        float4 v = ap[i];
        a[i * 4 + 0] = v.x; a[i * 4 + 1] = v.y;
        a[i * 4 + 2] = v.z; a[i * 4 + 3] = v.w;
    }

    float o[F_OUT];
#pragma unroll
    for (int m = 0; m < F_OUT; m++) {
        float acc = bs[m];
#pragma unroll
        for (int k = 0; k < H2; k++) acc += a[k] * Ws[k * F_OUT + m];
        o[m] = acc;
    }

    float mx = o[0];
#pragma unroll
    for (int m = 1; m < F_OUT; m++) mx = fmaxf(mx, o[m]);
    float sum = 0.f;
#pragma unroll
    for (int m = 0; m < F_OUT; m++) sum += __expf(o[m] - mx);
    float lse = mx + __logf(sum);

    float* op = out + (long)n * F_OUT;
#pragma unroll
    for (int m = 0; m < F_OUT; m++) op[m] = o[m] - lse;
}

// ---------------------------------------------------------------------------
// host launcher — kernel launches only
// ---------------------------------------------------------------------------
extern "C" void kernel_launch(void* const* d_in, const int* in_sizes, int n_in,
                              void* d_out, int out_size) {
    const float* x  = (const float*)d_in[0];
    const int*   ei = (const int*)d_in[1];      // int64 delivered as int32
    const float* W1 = (const float*)d_in[2];
    const float* b1 = (const float*)d_in[3];
    const float* W2 = (const float*)d_in[4];
    const float* b2 = (const float*)d_in[5];
    const float* W3 = (const float*)d_in[6];
    const float* b3 = (const float*)d_in[7];
    float* out = (float*)d_out;

    int N = in_sizes[0] / F_IN;
    int E = in_sizes[1] / 2;
    int nblk = (N + SCAN_B - 1) / SCAN_B;

    // degrees -> CSR -> dinv
    zero_deg_kernel<<<(N + 255) / 256, 256>>>(N);
    count_deg_kernel<<<(E + 255) / 256, 256>>>(ei, E, N);
    scan_partial_kernel<<<nblk, SCAN_B>>>(N);
    scan_bsum_kernel<<<1, SCAN_B>>>(nblk);
    scan_add_dinv_kernel<<<(N + 255) / 256, 256>>>(N);
    csr_fill_kernel<<<(E + 255) / 256, 256>>>(ei, E, N);

    // layer 1 GEMM (tf32 tensor cores, dinv fused)
    {
        dim3 grid(H1 / G1_BN, (N + G1_BM - 1) / G1_BM);
        gemm1_kernel<<<grid, 256>>>(x, W1, N);
    }

    // layer 1 aggregation + bias/relu + layer 2 GEMM, fused
    layer2_fused_kernel<<<(N + 15) / 16, 256>>>(b1, W2, N);

    // layer 2 aggregation (+ bias/relu + next dinv prescale)
    gather2_kernel<<<(N + 15) / 16, 256>>>(b2, N);

    // layer 3 aggregation + head
    gather3_kernel<<<(N + 15) / 16, 256>>>(N);
    final_kernel<<<(N + 255) / 256, 256>>>(W3, b3, out, N);
}

// round 8
// speedup vs baseline: 1.2891x; 1.2891x over previous
#include <cuda_runtime.h>
#include <math.h>
#include <stdint.h>

// Problem constants (fixed for this problem instance)
#define NMAX   50000
#define EMAX   800000
#define F_IN   512
#define H1     256
#define H2     16
#define F_OUT  40

#define SCAN_B 256

// Scratch (static device arrays; no allocation allowed)
__device__ float g_p1[NMAX * H1];   // dinv ⊙ (x @ W1)
__device__ float g_a1[NMAX * H1];   // relu(Ahat h1 + b1)
__device__ float g_p2[NMAX * H2];   // dinv ⊙ (a1 @ W2)
__device__ float g_p3[NMAX * H2];   // dinv ⊙ relu(Ahat h2 + b2)
__device__ float g_a3[NMAX * H2];   // Ahat r2
__device__ int   g_deg[NMAX];       // edge-only in-degree (no self loop)
__device__ int   g_rowstart[NMAX];
__device__ int   g_cursor[NMAX];
__device__ int   g_csrc[EMAX];      // src indices grouped by dst (CSR)
__device__ int   g_bsum[SCAN_B];
__device__ float g_dinv[NMAX];

__device__ __forceinline__ float4 f4add(float4 a, float4 b) {
    return make_float4(a.x + b.x, a.y + b.y, a.z + b.z, a.w + b.w);
}

// ---------------------------------------------------------------------------
// degree / scan / CSR fill / dinv
// ---------------------------------------------------------------------------
__global__ void zero_deg_kernel(int N) {
    int i = blockIdx.x * blockDim.x + threadIdx.x;
    if (i < N) g_deg[i] = 0;
}

__global__ void count_deg_kernel(const int* __restrict__ ei, int E, int N) {
    int e = blockIdx.x * blockDim.x + threadIdx.x;
    if (e < E) {
        int d = ei[E + e];
        if ((unsigned)d < (unsigned)N) atomicAdd(&g_deg[d], 1);
    }
}

__global__ void scan_partial_kernel(int N) {
    __shared__ int sd[SCAN_B];
    int t = threadIdx.x, b = blockIdx.x;
    int i = b * SCAN_B + t;
    int v = (i < N) ? g_deg[i] : 0;
    sd[t] = v;
    __syncthreads();
#pragma unroll
    for (int off = 1; off < SCAN_B; off <<= 1) {
        int x = (t >= off) ? sd[t - off] : 0;
        __syncthreads();
        sd[t] += x;
        __syncthreads();
    }
    if (i < N) g_rowstart[i] = sd[t] - v;       // exclusive
    if (t == SCAN_B - 1) g_bsum[b] = sd[t];
}

__global__ void scan_bsum_kernel(int nblk) {
    __shared__ int sd[SCAN_B];
    int t = threadIdx.x;
    int v = (t < nblk) ? g_bsum[t] : 0;
    sd[t] = v;
    __syncthreads();
#pragma unroll
    for (int off = 1; off < SCAN_B; off <<= 1) {
        int x = (t >= off) ? sd[t - off] : 0;
        __syncthreads();
        sd[t] += x;
        __syncthreads();
    }
    if (t < nblk) g_bsum[t] = sd[t] - v;
}

// merged: finalize rowstart, init cursor, compute dinv
__global__ void scan_add_dinv_kernel(int N) {
    int i = blockIdx.x * blockDim.x + threadIdx.x;
    if (i < N) {
        int r = g_rowstart[i] + g_bsum[i / SCAN_B];
        g_rowstart[i] = r;
        g_cursor[i] = r;
        g_dinv[i] = rsqrtf((float)(g_deg[i] + 1));   // +1 self-loop
    }
}

__global__ void csr_fill_kernel(const int* __restrict__ ei, int E, int N) {
    int e = blockIdx.x * blockDim.x + threadIdx.x;
    if (e < E) {
        int s = ei[e];
        int d = ei[E + e];
        if ((unsigned)s < (unsigned)N && (unsigned)d < (unsigned)N) {
            int pos = atomicAdd(&g_cursor[d], 1);
            g_csrc[pos] = s;
        }
    }
}

// ---------------------------------------------------------------------------
// GEMM1 (tf32 tensor cores): g_p1[N,256] = dinv ⊙ (A[N,512] @ B[512,256])
// block 128x128x16, 8 warps, warp tile 64x32 via mma.m16n8k8.tf32
// ---------------------------------------------------------------------------
#define G1_BM 128
#define G1_BN 128
#define G1_BK 16
#define AS_STRIDE 20
#define BS_STRIDE 132

__device__ __forceinline__ uint32_t f2tf32(float x) {
    uint32_t r;
    asm("cvt.rna.tf32.f32 %0, %1;" : "=r"(r) : "f"(x));
    return r;
}

__device__ __forceinline__ void mma_tf32(float c[4], const uint32_t a[4],
                                         const uint32_t b[2]) {
    asm volatile(
        "mma.sync.aligned.m16n8k8.row.col.f32.tf32.tf32.f32 "
        "{%0,%1,%2,%3}, {%4,%5,%6,%7}, {%8,%9}, {%0,%1,%2,%3};"
        : "+f"(c[0]), "+f"(c[1]), "+f"(c[2]), "+f"(c[3])
        : "r"(a[0]), "r"(a[1]), "r"(a[2]), "r"(a[3]), "r"(b[0]), "r"(b[1]));
}

__global__ void __launch_bounds__(256) gemm1_kernel(const float* __restrict__ A,
                                                    const float* __restrict__ B,
                                                    int N) {
    const int K = F_IN, M = H1;
    __shared__ uint32_t As[2][G1_BM * AS_STRIDE];
    __shared__ uint32_t Bs[2][G1_BK * BS_STRIDE];

    int tid = threadIdx.x;
    int lane = tid & 31;
    int w = tid >> 5;
    int wm = w >> 2;
    int wn = w & 3;
    int brow = blockIdx.y * G1_BM;
    int bcol = blockIdx.x * G1_BN;

    int arow = tid >> 1;
    int acg  = (tid & 1) * 4;
    int bk   = tid >> 4;
    int bn   = (tid & 15) * 4;

    float acc[4][4][4];
#pragma unroll
    for (int mi = 0; mi < 4; mi++)
#pragma unroll
        for (int ni = 0; ni < 4; ni++)
#pragma unroll
            for (int q = 0; q < 4; q++) acc[mi][ni][q] = 0.f;

    float4 a4a, a4b, b4a, b4b;
    {
        int gr = brow + arow;
        if (gr < N) {
            a4a = *(const float4*)&A[(long)gr * K + acg];
            a4b = *(const float4*)&A[(long)gr * K + acg + 8];
        } else {
            a4a = make_float4(0.f, 0.f, 0.f, 0.f);
            a4b = a4a;
        }
        b4a = *(const float4*)&B[(long)bk * M + bcol + bn];
        b4b = *(const float4*)&B[(long)bk * M + bcol + bn + 64];
    }
    {
        uint32_t* ap = &As[0][arow * AS_STRIDE + acg];
        ap[0] = f2tf32(a4a.x); ap[1] = f2tf32(a4a.y);
        ap[2] = f2tf32(a4a.z); ap[3] = f2tf32(a4a.w);
        ap[8] = f2tf32(a4b.x); ap[9] = f2tf32(a4b.y);
        ap[10] = f2tf32(a4b.z); ap[11] = f2tf32(a4b.w);
        uint32_t* bp = &Bs[0][bk * BS_STRIDE + bn];
        bp[0] = f2tf32(b4a.x); bp[1] = f2tf32(b4a.y);
        bp[2] = f2tf32(b4a.z); bp[3] = f2tf32(b4a.w);
        bp[64] = f2tf32(b4b.x); bp[65] = f2tf32(b4b.y);
        bp[66] = f2tf32(b4b.z); bp[67] = f2tf32(b4b.w);
    }
    __syncthreads();

    int buf = 0;
    for (int k0 = 0; k0 < K; k0 += G1_BK) {
        int knext = k0 + G1_BK;
        if (knext < K) {
            int gr = brow + arow;
            if (gr < N) {
                a4a = *(const float4*)&A[(long)gr * K + knext + acg];
                a4b = *(const float4*)&A[(long)gr * K + knext + acg + 8];
            } else {
                a4a = make_float4(0.f, 0.f, 0.f, 0.f);
                a4b = a4a;
            }
            b4a = *(const float4*)&B[(long)(knext + bk) * M + bcol + bn];
            b4b = *(const float4*)&B[(long)(knext + bk) * M + bcol + bn + 64];
        }

#pragma unroll
        for (int ks = 0; ks < 2; ks++) {
            int kk = ks * 8;
            uint32_t af[4][4], bf[4][2];
#pragma unroll
            for (int mi = 0; mi < 4; mi++) {
                int r = wm * 64 + mi * 16 + (lane >> 2);
                int c = kk + (lane & 3);
                af[mi][0] = As[buf][r * AS_STRIDE + c];
                af[mi][1] = As[buf][(r + 8) * AS_STRIDE + c];
                af[mi][2] = As[buf][r * AS_STRIDE + c + 4];
                af[mi][3] = As[buf][(r + 8) * AS_STRIDE + c + 4];
            }
#pragma unroll
            for (int ni = 0; ni < 4; ni++) {
                int c = wn * 32 + ni * 8 + (lane >> 2);
                int k1 = kk + (lane & 3);
                bf[ni][0] = Bs[buf][k1 * BS_STRIDE + c];
                bf[ni][1] = Bs[buf][(k1 + 4) * BS_STRIDE + c];
            }
#pragma unroll
            for (int mi = 0; mi < 4; mi++)
#pragma unroll
                for (int ni = 0; ni < 4; ni++)
                    mma_tf32(acc[mi][ni], af[mi], bf[ni]);
        }

        if (knext < K) {
            int nb = buf ^ 1;
            uint32_t* ap = &As[nb][arow * AS_STRIDE + acg];
            ap[0] = f2tf32(a4a.x); ap[1] = f2tf32(a4a.y);
            ap[2] = f2tf32(a4a.z); ap[3] = f2tf32(a4a.w);
            ap[8] = f2tf32(a4b.x); ap[9] = f2tf32(a4b.y);
            ap[10] = f2tf32(a4b.z); ap[11] = f2tf32(a4b.w);
            uint32_t* bp = &Bs[nb][bk * BS_STRIDE + bn];
            bp[0] = f2tf32(b4a.x); bp[1] = f2tf32(b4a.y);
            bp[2] = f2tf32(b4a.z); bp[3] = f2tf32(b4a.w);
            bp[64] = f2tf32(b4b.x); bp[65] = f2tf32(b4b.y);
            bp[66] = f2tf32(b4b.z); bp[67] = f2tf32(b4b.w);
            __syncthreads();
            buf = nb;
        }
    }

#pragma unroll
    for (int mi = 0; mi < 4; mi++) {
        int r0 = brow + wm * 64 + mi * 16 + (lane >> 2);
        int r1 = r0 + 8;
        float dv0 = (r0 < N) ? g_dinv[r0] : 0.f;
        float dv1 = (r1 < N) ? g_dinv[r1] : 0.f;
#pragma unroll
        for (int ni = 0; ni < 4; ni++) {
            int c = bcol + wn * 32 + ni * 8 + (lane & 3) * 2;
            if (r0 < N) {
                float2 v = make_float2(dv0 * acc[mi][ni][0], dv0 * acc[mi][ni][1]);
                *(float2*)&g_p1[(long)r0 * M + c] = v;
            }
            if (r1 < N) {
                float2 v = make_float2(dv1 * acc[mi][ni][2], dv1 * acc[mi][ni][3]);
                *(float2*)&g_p1[(long)r1 * M + c] = v;
            }
        }
    }
}

// ---------------------------------------------------------------------------
// gather1 (F=256, float4): a1[d] = relu(dinv[d]*(p1[d]+sum p1[s]) + b1)
// 64 threads per node (float4 each), 4 nodes per 256-thread block
// ---------------------------------------------------------------------------
__global__ void __launch_bounds__(256) gather1_kernel(const float* __restrict__ b1, int N) {
    int tid = threadIdx.x;
    int d = blockIdx.x * 4 + (tid >> 6);
    int f4 = (tid & 63);               // float4 index: feature = 4*f4
    if (d >= N) return;

    const float4* p1v = (const float4*)g_p1;
    long rowbase = (long)d * (H1 / 4);

    int start = g_rowstart[d];
    int deg = g_deg[d];

    float4 acc0 = p1v[rowbase + f4];   // self loop (p1 pre-scaled by dinv[s])
    float4 acc1 = make_float4(0.f, 0.f, 0.f, 0.f);
    int j = 0;
    for (; j + 1 < deg; j += 2) {
        int s0 = __ldg(&g_csrc[start + j]);
        int s1 = __ldg(&g_csrc[start + j + 1]);
        acc0 = f4add(acc0, p1v[(long)s0 * (H1 / 4) + f4]);
        acc1 = f4add(acc1, p1v[(long)s1 * (H1 / 4) + f4]);
    }
    if (j < deg) {
        int s0 = __ldg(&g_csrc[start + j]);
        acc0 = f4add(acc0, p1v[(long)s0 * (H1 / 4) + f4]);
    }

    float dv = g_dinv[d];
    float4 bb = ((const float4*)b1)[f4];
    float4 v = make_float4(dv * (acc0.x + acc1.x) + bb.x,
                           dv * (acc0.y + acc1.y) + bb.y,
                           dv * (acc0.z + acc1.z) + bb.z,
                           dv * (acc0.w + acc1.w) + bb.w);
    v.x = v.x > 0.f ? v.x : 0.f;
    v.y = v.y > 0.f ? v.y : 0.f;
    v.z = v.z > 0.f ? v.z : 0.f;
    v.w = v.w > 0.f ? v.w : 0.f;
    ((float4*)g_a1)[rowbase + f4] = v;
}

// ---------------------------------------------------------------------------
// GEMM2: g_p2 = dinv ⊙ (a1 @ W2)   (K=256, M=16)
// ---------------------------------------------------------------------------
__global__ void gemm2_kernel(const float* __restrict__ W, int N) {
    const int K = H1, M = H2;
    __shared__ float Ws[K * M];        // 16 KB
    __shared__ float Asm[16][K];       // 16 KB

    int tx = threadIdx.x;  // 0..15  (col m)
    int ty = threadIdx.y;  // 0..15  (local row)
    int tid = ty * 16 + tx;

    for (int i = tid; i < K * M; i += 256) Ws[i] = W[i];

    int row0 = blockIdx.x * 16;
    for (int i = tid; i < 16 * K; i += 256) {
        int r = i / K, c = i % K;
        int gr = row0 + r;
        Asm[r][c] = (gr < N) ? g_a1[(long)gr * K + c] : 0.f;
    }
    __syncthreads();

    int n = row0 + ty;
    if (n >= N) return;

    float acc = 0.f;
#pragma unroll 8
    for (int k = 0; k < K; k++) acc += Asm[ty][k] * Ws[k * M + tx];
    g_p2[(long)n * M + tx] = g_dinv[n] * acc;
}

// ---------------------------------------------------------------------------
// gather2 (F=16, float4): p3[d] = dinv[d]*relu(dinv[d]*(p2[d]+sum p2[s]) + b2)
// 4 threads per node, 64 nodes per 256-thread block
// ---------------------------------------------------------------------------
__global__ void __launch_bounds__(256) gather2_kernel(const float* __restrict__ b2, int N) {
    int tid = threadIdx.x;
    int d = blockIdx.x * 64 + (tid >> 2);
    int f4 = tid & 3;
    if (d >= N) return;

    const float4* p2v = (const float4*)g_p2;
    int start = g_rowstart[d];
    int deg = g_deg[d];

    float4 acc0 = p2v[(long)d * 4 + f4];
    float4 acc1 = make_float4(0.f, 0.f, 0.f, 0.f);
    int j = 0;
    for (; j + 1 < deg; j += 2) {
        int s0 = __ldg(&g_csrc[start + j]);
        int s1 = __ldg(&g_csrc[start + j + 1]);
        acc0 = f4add(acc0, p2v[(long)s0 * 4 + f4]);
        acc1 = f4add(acc1, p2v[(long)s1 * 4 + f4]);
    }
    if (j < deg) {
        int s0 = __ldg(&g_csrc[start + j]);
        acc0 = f4add(acc0, p2v[(long)s0 * 4 + f4]);
    }

    float dv = g_dinv[d];
    float4 bb = ((const float4*)b2)[f4];
    float4 v = make_float4(dv * (acc0.x + acc1.x) + bb.x,
                           dv * (acc0.y + acc1.y) + bb.y,
                           dv * (acc0.z + acc1.z) + bb.z,
                           dv * (acc0.w + acc1.w) + bb.w);
    v.x = dv * (v.x > 0.f ? v.x : 0.f);
    v.y = dv * (v.y > 0.f ? v.y : 0.f);
    v.z = dv * (v.z > 0.f ? v.z : 0.f);
    v.w = dv * (v.w > 0.f ? v.w : 0.f);
    ((float4*)g_p3)[(long)d * 4 + f4] = v;
}

// ---------------------------------------------------------------------------
// gather3 (F=16, float4): a3[d] = dinv[d]*(p3[d]+sum p3[s])
// ---------------------------------------------------------------------------
__global__ void __launch_bounds__(256) gather3_kernel(int N) {
    int tid = threadIdx.x;
    int d = blockIdx.x * 64 + (tid >> 2);
    int f4 = tid & 3;
    if (d >= N) return;

    const float4* p3v = (const float4*)g_p3;
    int start = g_rowstart[d];
    int deg = g_deg[d];

    float4 acc0 = p3v[(long)d * 4 + f4];
    float4 acc1 = make_float4(0.f, 0.f, 0.f, 0.f);
    int j = 0;
    for (; j + 1 < deg; j += 2) {
        int s0 = __ldg(&g_csrc[start + j]);
        int s1 = __ldg(&g_csrc[start + j + 1]);
        acc0 = f4add(acc0, p3v[(long)s0 * 4 + f4]);
        acc1 = f4add(acc1, p3v[(long)s1 * 4 + f4]);
    }
    if (j < deg) {
        int s0 = __ldg(&g_csrc[start + j]);
        acc0 = f4add(acc0, p3v[(long)s0 * 4 + f4]);
    }

    float dv = g_dinv[d];
    float4 v = make_float4(dv * (acc0.x + acc1.x), dv * (acc0.y + acc1.y),
                           dv * (acc0.z + acc1.z), dv * (acc0.w + acc1.w));
    ((float4*)g_a3)[(long)d * 4 + f4] = v;
}

// ---------------------------------------------------------------------------
// final: o = g_a3 @ W3 + b3 ; log_softmax ; one thread per node
// ---------------------------------------------------------------------------
__global__ void final_kernel(const float* __restrict__ W3,
                             const float* __restrict__ b3,
                             float* __restrict__ out, int N) {
    __shared__ float Ws[H2 * F_OUT];
    __shared__ float bs[F_OUT];
    int tid = threadIdx.x;
    for (int i = tid; i < H2 * F_OUT; i += blockDim.x) Ws[i] = W3[i];
    if (tid < F_OUT) bs[tid] = b3[tid];
    __syncthreads();

    int n = blockIdx.x * blockDim.x + tid;
    if (n >= N) return;

    float a[H2];
    const float4* ap = (const float4*)(g_a3 + (long)n * H2);
#pragma unroll
    for (int i = 0; i < 4; i++) {
        float4 v = ap[i];
        a[i * 4 + 0] = v.x; a[i * 4 + 1] = v.y;
        a[i * 4 + 2] = v.z; a[i * 4 + 3] = v.w;
    }

    float o[F_OUT];
#pragma unroll
    for (int m = 0; m < F_OUT; m++) {
        float acc = bs[m];
#pragma unroll
        for (int k = 0; k < H2; k++) acc += a[k] * Ws[k * F_OUT + m];
        o[m] = acc;
    }

    float mx = o[0];
#pragma unroll
    for (int m = 1; m < F_OUT; m++) mx = fmaxf(mx, o[m]);
    float sum = 0.f;
#pragma unroll
    for (int m = 0; m < F_OUT; m++) sum += __expf(o[m] - mx);
    float lse = mx + __logf(sum);

    float* op = out + (long)n * F_OUT;
#pragma unroll
    for (int m = 0; m < F_OUT; m++) op[m] = o[m] - lse;
}

// ---------------------------------------------------------------------------
// host launcher — kernel launches only
// ---------------------------------------------------------------------------
extern "C" void kernel_launch(void* const* d_in, const int* in_sizes, int n_in,
                              void* d_out, int out_size) {
    const float* x  = (const float*)d_in[0];
    const int*   ei = (const int*)d_in[1];      // int64 delivered as int32
    const float* W1 = (const float*)d_in[2];
    const float* b1 = (const float*)d_in[3];
    const float* W2 = (const float*)d_in[4];
    const float* b2 = (const float*)d_in[5];
    const float* W3 = (const float*)d_in[6];
    const float* b3 = (const float*)d_in[7];
    float* out = (float*)d_out;

    int N = in_sizes[0] / F_IN;
    int E = in_sizes[1] / 2;
    int nblk = (N + SCAN_B - 1) / SCAN_B;

    // degrees -> CSR -> dinv
    zero_deg_kernel<<<(N + 255) / 256, 256>>>(N);
    count_deg_kernel<<<(E + 255) / 256, 256>>>(ei, E, N);
    scan_partial_kernel<<<nblk, SCAN_B>>>(N);
    scan_bsum_kernel<<<1, SCAN_B>>>(nblk);
    scan_add_dinv_kernel<<<(N + 255) / 256, 256>>>(N);
    csr_fill_kernel<<<(E + 255) / 256, 256>>>(ei, E, N);

    // layer 1 GEMM (tf32 tensor cores, dinv fused)
    {
        dim3 grid(H1 / G1_BN, (N + G1_BM - 1) / G1_BM);
        gemm1_kernel<<<grid, 256>>>(x, W1, N);
    }

    // layer 1 aggregation (+bias/relu), float4, 4 nodes/block
    gather1_kernel<<<(N + 3) / 4, 256>>>(b1, N);

    // layer 2
    gemm2_kernel<<<(N + 15) / 16, dim3(16, 16)>>>(W2, N);
    gather2_kernel<<<(N + 63) / 64, 256>>>(b2, N);

    // layer 3 aggregation + head
    gather3_kernel<<<(N + 63) / 64, 256>>>(N);
    final_kernel<<<(N + 255) / 256, 256>>>(W3, b3, out, N);
}

// round 9
// speedup vs baseline: 1.4183x; 1.1002x over previous
#include <cuda_runtime.h>
#include <math.h>
#include <stdint.h>

// Problem constants (fixed for this problem instance)
#define NMAX   50000
#define EMAX   800000
#define F_IN   512
#define H1     256
#define H2     16
#define F_OUT  40

#define SCAN_B 256

// Scratch (static device arrays; no allocation allowed)
__device__ float g_p1[NMAX * H1];   // dinv ⊙ (x @ W1)
__device__ float g_a1[NMAX * H1];   // relu(Ahat h1 + b1)
__device__ float g_p2[NMAX * H2];   // dinv ⊙ (a1 @ W2)
__device__ float g_p3[NMAX * H2];   // dinv ⊙ relu(Ahat h2 + b2)
__device__ float g_a3[NMAX * H2];   // Ahat r2
__device__ int   g_deg[NMAX];       // edge-only in-degree (no self loop)
__device__ int   g_rowstart[NMAX];
__device__ int   g_cursor[NMAX];
__device__ int   g_csrc[EMAX];      // src indices grouped by dst (CSR)
__device__ int   g_bsum[SCAN_B];
__device__ float g_dinv[NMAX];

__device__ __forceinline__ float4 f4add(float4 a, float4 b) {
    return make_float4(a.x + b.x, a.y + b.y, a.z + b.z, a.w + b.w);
}

// ---------------------------------------------------------------------------
// degree / dinv / scan / CSR fill
// ---------------------------------------------------------------------------
__global__ void zero_deg_kernel(int N) {
    int i = blockIdx.x * blockDim.x + threadIdx.x;
    if (i < N) g_deg[i] = 0;
}

__global__ void count_deg_kernel(const int* __restrict__ ei, int E, int N) {
    int e = blockIdx.x * blockDim.x + threadIdx.x;
    if (e < E) {
        int d = ei[E + e];
        if ((unsigned)d < (unsigned)N) atomicAdd(&g_deg[d], 1);
    }
}

__global__ void dinv_kernel(int N) {
    int i = blockIdx.x * blockDim.x + threadIdx.x;
    if (i < N) g_dinv[i] = rsqrtf((float)(g_deg[i] + 1));   // +1 self-loop
}

__global__ void scan_partial_kernel(int N) {
    __shared__ int sd[SCAN_B];
    int t = threadIdx.x, b = blockIdx.x;
    int i = b * SCAN_B + t;
    int v = (i < N) ? g_deg[i] : 0;
    sd[t] = v;
    __syncthreads();
#pragma unroll
    for (int off = 1; off < SCAN_B; off <<= 1) {
        int x = (t >= off) ? sd[t - off] : 0;
        __syncthreads();
        sd[t] += x;
        __syncthreads();
    }
    if (i < N) g_rowstart[i] = sd[t] - v;       // exclusive
    if (t == SCAN_B - 1) g_bsum[b] = sd[t];
}

__global__ void scan_bsum_kernel(int nblk) {
    __shared__ int sd[SCAN_B];
    int t = threadIdx.x;
    int v = (t < nblk) ? g_bsum[t] : 0;
    sd[t] = v;
    __syncthreads();
#pragma unroll
    for (int off = 1; off < SCAN_B; off <<= 1) {
        int x = (t >= off) ? sd[t - off] : 0;
        __syncthreads();
        sd[t] += x;
        __syncthreads();
    }
    if (t < nblk) g_bsum[t] = sd[t] - v;
}

__global__ void scan_add_kernel(int N) {
    int i = blockIdx.x * blockDim.x + threadIdx.x;
    if (i < N) {
        int r = g_rowstart[i] + g_bsum[i / SCAN_B];
        g_rowstart[i] = r;
        g_cursor[i] = r;
    }
}

__global__ void csr_fill_kernel(const int* __restrict__ ei, int E, int N) {
    int e = blockIdx.x * blockDim.x + threadIdx.x;
    if (e < E) {
        int s = ei[e];
        int d = ei[E + e];
        if ((unsigned)s < (unsigned)N && (unsigned)d < (unsigned)N) {
            int pos = atomicAdd(&g_cursor[d], 1);
            g_csrc[pos] = s;
        }
    }
}

// ---------------------------------------------------------------------------
// GEMM1 (tf32 tensor cores + cp.async 3-stage): g_p1 = dinv ⊙ (A @ B)
// block 128x128x16, 8 warps, warp tile 64x32 via mma.m16n8k8.tf32
// fp32 bits fed directly to mma (tf32 truncation, no cvt)
// ---------------------------------------------------------------------------
#define G1_BM 128
#define G1_BN 128
#define G1_BK 16
#define G1_KT (F_IN / G1_BK)   // 32 k-tiles
#define STAGES 3
#define AS_STRIDE 20
#define BS_STRIDE 132

__device__ __forceinline__ void mma_tf32(float c[4], const uint32_t a[4],
                                         const uint32_t b[2]) {
    asm volatile(
        "mma.sync.aligned.m16n8k8.row.col.f32.tf32.tf32.f32 "
        "{%0,%1,%2,%3}, {%4,%5,%6,%7}, {%8,%9}, {%0,%1,%2,%3};"
        : "+f"(c[0]), "+f"(c[1]), "+f"(c[2]), "+f"(c[3])
        : "r"(a[0]), "r"(a[1]), "r"(a[2]), "r"(a[3]), "r"(b[0]), "r"(b[1]));
}

__device__ __forceinline__ void cp_async16(uint32_t smem_dst, const void* gsrc,
                                           int src_bytes) {
    asm volatile("cp.async.ca.shared.global [%0], [%1], 16, %2;"
                 :: "r"(smem_dst), "l"(gsrc), "r"(src_bytes));
}

__global__ void __launch_bounds__(256) gemm1_kernel(const float* __restrict__ A,
                                                    const float* __restrict__ B,
                                                    int N) {
    const int K = F_IN, M = H1;
    __shared__ uint32_t As[STAGES][G1_BM * AS_STRIDE];   // 30 KB
    __shared__ uint32_t Bs[STAGES][G1_BK * BS_STRIDE];   // ~25 KB

    int tid = threadIdx.x;
    int lane = tid & 31;
    int w = tid >> 5;
    int wm = w >> 2;
    int wn = w & 3;
    int brow = blockIdx.y * G1_BM;
    int bcol = blockIdx.x * G1_BN;

    int arow = tid >> 1;               // 0..127
    int acg  = (tid & 1) * 4;          // 0 or 4 (plus +8)
    int bk   = tid >> 4;               // 0..15
    int bn   = (tid & 15) * 4;         // 0..60 (plus +64)

    int gr = brow + arow;
    int a_ok = (gr < N) ? 16 : 0;
    const float* a_src0 = &A[(long)gr * K + acg];

    // issue loads for a stage
    auto load_stage = [&](int st, int k0) {
        uint32_t ad = (uint32_t)__cvta_generic_to_shared(&As[st][arow * AS_STRIDE + acg]);
        cp_async16(ad, a_src0 + k0, a_ok);
        cp_async16(ad + 32, a_src0 + k0 + 8, a_ok);
        uint32_t bd = (uint32_t)__cvta_generic_to_shared(&Bs[st][bk * BS_STRIDE + bn]);
        cp_async16(bd, &B[(long)(k0 + bk) * M + bcol + bn], 16);
        cp_async16(bd + 256, &B[(long)(k0 + bk) * M + bcol + bn + 64], 16);
    };

    float acc[4][4][4];
#pragma unroll
    for (int mi = 0; mi < 4; mi++)
#pragma unroll
        for (int ni = 0; ni < 4; ni++)
#pragma unroll
            for (int q = 0; q < 4; q++) acc[mi][ni][q] = 0.f;

    // prologue: stages 0,1
    load_stage(0, 0);
    asm volatile("cp.async.commit_group;");
    load_stage(1, G1_BK);
    asm volatile("cp.async.commit_group;");

    for (int kt = 0; kt < G1_KT; kt++) {
        asm volatile("cp.async.wait_group 1;");
        __syncthreads();

        int buf = kt % STAGES;
#pragma unroll
        for (int ks = 0; ks < 2; ks++) {
            int kk = ks * 8;
            uint32_t af[4][4], bf[4][2];
#pragma unroll
            for (int mi = 0; mi < 4; mi++) {
                int r = wm * 64 + mi * 16 + (lane >> 2);
                int c = kk + (lane & 3);
                af[mi][0] = As[buf][r * AS_STRIDE + c];
                af[mi][1] = As[buf][(r + 8) * AS_STRIDE + c];
                af[mi][2] = As[buf][r * AS_STRIDE + c + 4];
                af[mi][3] = As[buf][(r + 8) * AS_STRIDE + c + 4];
            }
#pragma unroll
            for (int ni = 0; ni < 4; ni++) {
                int c = wn * 32 + ni * 8 + (lane >> 2);
                int k1 = kk + (lane & 3);
                bf[ni][0] = Bs[buf][k1 * BS_STRIDE + c];
                bf[ni][1] = Bs[buf][(k1 + 4) * BS_STRIDE + c];
            }
#pragma unroll
            for (int mi = 0; mi < 4; mi++)
#pragma unroll
                for (int ni = 0; ni < 4; ni++)
                    mma_tf32(acc[mi][ni], af[mi], bf[ni]);
        }
        __syncthreads();

        if (kt + 2 < G1_KT) load_stage((kt + 2) % STAGES, (kt + 2) * G1_BK);
        asm volatile("cp.async.commit_group;");
    }

    // epilogue: scale by dinv[row], write p1
#pragma unroll
    for (int mi = 0; mi < 4; mi++) {
        int r0 = brow + wm * 64 + mi * 16 + (lane >> 2);
        int r1 = r0 + 8;
        float dv0 = (r0 < N) ? g_dinv[r0] : 0.f;
        float dv1 = (r1 < N) ? g_dinv[r1] : 0.f;
#pragma unroll
        for (int ni = 0; ni < 4; ni++) {
            int c = bcol + wn * 32 + ni * 8 + (lane & 3) * 2;
            if (r0 < N) {
                float2 v = make_float2(dv0 * acc[mi][ni][0], dv0 * acc[mi][ni][1]);
                *(float2*)&g_p1[(long)r0 * M + c] = v;
            }
            if (r1 < N) {
                float2 v = make_float2(dv1 * acc[mi][ni][2], dv1 * acc[mi][ni][3]);
                *(float2*)&g_p1[(long)r1 * M + c] = v;
            }
        }
    }
}

// ---------------------------------------------------------------------------
// gather1 (F=256, float4): a1[d] = relu(dinv[d]*(p1[d]+sum p1[s]) + b1)
// 64 threads per node (float4 each), 4 nodes per 256-thread block
// ---------------------------------------------------------------------------
__global__ void __launch_bounds__(256) gather1_kernel(const float* __restrict__ b1, int N) {
    int tid = threadIdx.x;
    int d = blockIdx.x * 4 + (tid >> 6);
    int f4 = (tid & 63);
    if (d >= N) return;

    const float4* p1v = (const float4*)g_p1;
    long rowbase = (long)d * (H1 / 4);

    int start = g_rowstart[d];
    int deg = g_deg[d];

    float4 acc0 = p1v[rowbase + f4];   // self loop (p1 pre-scaled by dinv[s])
    float4 acc1 = make_float4(0.f, 0.f, 0.f, 0.f);
    int j = 0;
    for (; j + 1 < deg; j += 2) {
        int s0 = __ldg(&g_csrc[start + j]);
        int s1 = __ldg(&g_csrc[start + j + 1]);
        acc0 = f4add(acc0, p1v[(long)s0 * (H1 / 4) + f4]);
        acc1 = f4add(acc1, p1v[(long)s1 * (H1 / 4) + f4]);
    }
    if (j < deg) {
        int s0 = __ldg(&g_csrc[start + j]);
        acc0 = f4add(acc0, p1v[(long)s0 * (H1 / 4) + f4]);
    }

    float dv = g_dinv[d];
    float4 bb = ((const float4*)b1)[f4];
    float4 v = make_float4(dv * (acc0.x + acc1.x) + bb.x,
                           dv * (acc0.y + acc1.y) + bb.y,
                           dv * (acc0.z + acc1.z) + bb.z,
                           dv * (acc0.w + acc1.w) + bb.w);
    v.x = v.x > 0.f ? v.x : 0.f;
    v.y = v.y > 0.f ? v.y : 0.f;
    v.z = v.z > 0.f ? v.z : 0.f;
    v.w = v.w > 0.f ? v.w : 0.f;
    ((float4*)g_a1)[rowbase + f4] = v;
}

// ---------------------------------------------------------------------------
// GEMM2: one thread per node. p2[n] = dinv[n] * (a1[n] @ W2)
// W2 in smem ([k][m], broadcast LDS), a1 row streamed as float4.
// ---------------------------------------------------------------------------
__global__ void __launch_bounds__(256) gemm2_kernel(const float* __restrict__ W, int N) {
    __shared__ float Ws[H1 * H2];      // 16 KB
    int tid = threadIdx.x;
    for (int i = tid; i < H1 * H2; i += 256) Ws[i] = W[i];
    __syncthreads();

    int n = blockIdx.x * 256 + tid;
    if (n >= N) return;

    float acc[H2];
#pragma unroll
    for (int m = 0; m < H2; m++) acc[m] = 0.f;

    const float4* arow = (const float4*)(g_a1 + (long)n * H1);
    for (int k4 = 0; k4 < H1 / 4; k4++) {
        float4 a = arow[k4];
        const float* wk = &Ws[k4 * 4 * H2];
#pragma unroll
        for (int m = 0; m < H2; m++) {
            acc[m] += a.x * wk[m] + a.y * wk[H2 + m] +
                      a.z * wk[2 * H2 + m] + a.w * wk[3 * H2 + m];
        }
    }

    float dv = g_dinv[n];
    float* op = &g_p2[(long)n * H2];
#pragma unroll
    for (int m4 = 0; m4 < 4; m4++) {
        float4 v = make_float4(dv * acc[m4 * 4 + 0], dv * acc[m4 * 4 + 1],
                               dv * acc[m4 * 4 + 2], dv * acc[m4 * 4 + 3]);
        *(float4*)&op[m4 * 4] = v;
    }
}

// ---------------------------------------------------------------------------
// gather2 (F=16, float4): p3[d] = dinv[d]*relu(dinv[d]*(p2[d]+sum p2[s]) + b2)
// ---------------------------------------------------------------------------
__global__ void __launch_bounds__(256) gather2_kernel(const float* __restrict__ b2, int N) {
    int tid = threadIdx.x;
    int d = blockIdx.x * 64 + (tid >> 2);
    int f4 = tid & 3;
    if (d >= N) return;

    const float4* p2v = (const float4*)g_p2;
    int start = g_rowstart[d];
    int deg = g_deg[d];

    float4 acc0 = p2v[(long)d * 4 + f4];
    float4 acc1 = make_float4(0.f, 0.f, 0.f, 0.f);
    int j = 0;
    for (; j + 1 < deg; j += 2) {
        int s0 = __ldg(&g_csrc[start + j]);
        int s1 = __ldg(&g_csrc[start + j + 1]);
        acc0 = f4add(acc0, p2v[(long)s0 * 4 + f4]);
        acc1 = f4add(acc1, p2v[(long)s1 * 4 + f4]);
    }
    if (j < deg) {
        int s0 = __ldg(&g_csrc[start + j]);
        acc0 = f4add(acc0, p2v[(long)s0 * 4 + f4]);
    }

    float dv = g_dinv[d];
    float4 bb = ((const float4*)b2)[f4];
    float4 v = make_float4(dv * (acc0.x + acc1.x) + bb.x,
                           dv * (acc0.y + acc1.y) + bb.y,
                           dv * (acc0.z + acc1.z) + bb.z,
                           dv * (acc0.w + acc1.w) + bb.w);
    v.x = dv * (v.x > 0.f ? v.x : 0.f);
    v.y = dv * (v.y > 0.f ? v.y : 0.f);
    v.z = dv * (v.z > 0.f ? v.z : 0.f);
    v.w = dv * (v.w > 0.f ? v.w : 0.f);
    ((float4*)g_p3)[(long)d * 4 + f4] = v;
}

// ---------------------------------------------------------------------------
// gather3 (F=16, float4): a3[d] = dinv[d]*(p3[d]+sum p3[s])
// ---------------------------------------------------------------------------
__global__ void __launch_bounds__(256) gather3_kernel(int N) {
    int tid = threadIdx.x;
    int d = blockIdx.x * 64 + (tid >> 2);
    int f4 = tid & 3;
    if (d >= N) return;

    const float4* p3v = (const float4*)g_p3;
    int start = g_rowstart[d];
    int deg = g_deg[d];

    float4 acc0 = p3v[(long)d * 4 + f4];
    float4 acc1 = make_float4(0.f, 0.f, 0.f, 0.f);
    int j = 0;
    for (; j + 1 < deg; j += 2) {
        int s0 = __ldg(&g_csrc[start + j]);
        int s1 = __ldg(&g_csrc[start + j + 1]);
        acc0 = f4add(acc0, p3v[(long)s0 * 4 + f4]);
        acc1 = f4add(acc1, p3v[(long)s1 * 4 + f4]);
    }
    if (j < deg) {
        int s0 = __ldg(&g_csrc[start + j]);
        acc0 = f4add(acc0, p3v[(long)s0 * 4 + f4]);
    }

    float dv = g_dinv[d];
    float4 v = make_float4(dv * (acc0.x + acc1.x), dv * (acc0.y + acc1.y),
                           dv * (acc0.z + acc1.z), dv * (acc0.w + acc1.w));
    ((float4*)g_a3)[(long)d * 4 + f4] = v;
}

// ---------------------------------------------------------------------------
// final: o = g_a3 @ W3 + b3 ; log_softmax ; one thread per node
// ---------------------------------------------------------------------------
__global__ void final_kernel(const float* __restrict__ W3,
                             const float* __restrict__ b3,
                             float* __restrict__ out, int N) {
    __shared__ float Ws[H2 * F_OUT];
    __shared__ float bs[F_OUT];
    int tid = threadIdx.x;
    for (int i = tid; i < H2 * F_OUT; i += blockDim.x) Ws[i] = W3[i];
    if (tid < F_OUT) bs[tid] = b3[tid];
    __syncthreads();

    int n = blockIdx.x * blockDim.x + tid;
    if (n >= N) return;

    float a[H2];
    const float4* ap = (const float4*)(g_a3 + (long)n * H2);
#pragma unroll
    for (int i = 0; i < 4; i++) {
        float4 v = ap[i];
        a[i * 4 + 0] = v.x; a[i * 4 + 1] = v.y;
        a[i * 4 + 2] = v.z; a[i * 4 + 3] = v.w;
    }

    float o[F_OUT];
#pragma unroll
    for (int m = 0; m < F_OUT; m++) {
        float acc = bs[m];
#pragma unroll
        for (int k = 0; k < H2; k++) acc += a[k] * Ws[k * F_OUT + m];
        o[m] = acc;
    }

    float mx = o[0];
#pragma unroll
    for (int m = 1; m < F_OUT; m++) mx = fmaxf(mx, o[m]);
    float sum = 0.f;
#pragma unroll
    for (int m = 0; m < F_OUT; m++) sum += __expf(o[m] - mx);
    float lse = mx + __logf(sum);

    float* op = out + (long)n * F_OUT;
#pragma unroll
    for (int m = 0; m < F_OUT; m++) op[m] = o[m] - lse;
}

// ---------------------------------------------------------------------------
// host launcher — kernel launches only
// (gemm1 at launch position 4 so the ncu capture window lands on it)
// ---------------------------------------------------------------------------
extern "C" void kernel_launch(void* const* d_in, const int* in_sizes, int n_in,
                              void* d_out, int out_size) {
    const float* x  = (const float*)d_in[0];
    const int*   ei = (const int*)d_in[1];      // int64 delivered as int32
    const float* W1 = (const float*)d_in[2];
    const float* b1 = (const float*)d_in[3];
    const float* W2 = (const float*)d_in[4];
    const float* b2 = (const float*)d_in[5];
    const float* W3 = (const float*)d_in[6];
    const float* b3 = (const float*)d_in[7];
    float* out = (float*)d_out;

    int N = in_sizes[0] / F_IN;
    int E = in_sizes[1] / 2;
    int nblk = (N + SCAN_B - 1) / SCAN_B;

    // 1-3: degree + dinv (gemm1 epilogue needs dinv)
    zero_deg_kernel<<<(N + 255) / 256, 256>>>(N);
    count_deg_kernel<<<(E + 255) / 256, 256>>>(ei, E, N);
    dinv_kernel<<<(N + 255) / 256, 256>>>(N);

    // 4: layer 1 GEMM (tf32 + cp.async pipeline, dinv fused)
    {
        dim3 grid(H1 / G1_BN, (N + G1_BM - 1) / G1_BM);
        gemm1_kernel<<<grid, 256>>>(x, W1, N);
    }

    // 5-8: CSR build (overlaps nothing, but independent of gemm1 result)
    scan_partial_kernel<<<nblk, SCAN_B>>>(N);
    scan_bsum_kernel<<<1, SCAN_B>>>(nblk);
    scan_add_kernel<<<(N + 255) / 256, 256>>>(N);
    csr_fill_kernel<<<(E + 255) / 256, 256>>>(ei, E, N);

    // 9: layer 1 aggregation (+bias/relu)
    gather1_kernel<<<(N + 3) / 4, 256>>>(b1, N);

    // 10-11: layer 2
    gemm2_kernel<<<(N + 255) / 256, 256>>>(W2, N);
    gather2_kernel<<<(N + 63) / 64, 256>>>(b2, N);

    // 12-13: layer 3 aggregation + head
    gather3_kernel<<<(N + 63) / 64, 256>>>(N);
    final_kernel<<<(N + 255) / 256, 256>>>(W3, b3, out, N);
}

// round 10
// speedup vs baseline: 1.5300x; 1.0788x over previous
#include <cuda_runtime.h>
#include <math.h>
#include <stdint.h>

// Problem constants (fixed for this problem instance)
#define NMAX   50000
#define EMAX   800000
#define F_IN   512
#define H1     256
#define H2     16
#define F_OUT  40

#define SCAN_B 256

// Scratch (static device arrays; no allocation allowed)
__device__ float g_p1[NMAX * H1];   // dinv ⊙ (x @ W1)
__device__ float g_a1[NMAX * H1];   // relu(Ahat h1 + b1)
__device__ float g_p2[NMAX * H2];   // dinv ⊙ (a1 @ W2)
__device__ float g_p3[NMAX * H2];   // dinv ⊙ relu(Ahat h2 + b2)
__device__ float g_a3[NMAX * H2];   // Ahat r2
__device__ int   g_deg[NMAX];       // edge-only in-degree (no self loop)
__device__ int   g_rowstart[NMAX];
__device__ int   g_cursor[NMAX];
__device__ int   g_csrc[EMAX];      // src indices grouped by dst (CSR)
__device__ int   g_bsum[SCAN_B];
__device__ float g_dinv[NMAX];

__device__ __forceinline__ float4 f4add(float4 a, float4 b) {
    return make_float4(a.x + b.x, a.y + b.y, a.z + b.z, a.w + b.w);
}

// ---------------------------------------------------------------------------
// degree / dinv / scan / CSR fill
// ---------------------------------------------------------------------------
__global__ void zero_deg_kernel(int N) {
    int i = blockIdx.x * blockDim.x + threadIdx.x;
    if (i < N) g_deg[i] = 0;
}

__global__ void count_deg_kernel(const int* __restrict__ ei, int E, int N) {
    int e = blockIdx.x * blockDim.x + threadIdx.x;
    if (e < E) {
        int d = ei[E + e];
        if ((unsigned)d < (unsigned)N) atomicAdd(&g_deg[d], 1);
    }
}

__global__ void dinv_kernel(int N) {
    int i = blockIdx.x * blockDim.x + threadIdx.x;
    if (i < N) g_dinv[i] = rsqrtf((float)(g_deg[i] + 1));   // +1 self-loop
}

__global__ void scan_partial_kernel(int N) {
    __shared__ int sd[SCAN_B];
    int t = threadIdx.x, b = blockIdx.x;
    int i = b * SCAN_B + t;
    int v = (i < N) ? g_deg[i] : 0;
    sd[t] = v;
    __syncthreads();
#pragma unroll
    for (int off = 1; off < SCAN_B; off <<= 1) {
        int x = (t >= off) ? sd[t - off] : 0;
        __syncthreads();
        sd[t] += x;
        __syncthreads();
    }
    if (i < N) g_rowstart[i] = sd[t] - v;       // exclusive
    if (t == SCAN_B - 1) g_bsum[b] = sd[t];
}

__global__ void scan_bsum_kernel(int nblk) {
    __shared__ int sd[SCAN_B];
    int t = threadIdx.x;
    int v = (t < nblk) ? g_bsum[t] : 0;
    sd[t] = v;
    __syncthreads();
#pragma unroll
    for (int off = 1; off < SCAN_B; off <<= 1) {
        int x = (t >= off) ? sd[t - off] : 0;
        __syncthreads();
        sd[t] += x;
        __syncthreads();
    }
    if (t < nblk) g_bsum[t] = sd[t] - v;
}

__global__ void scan_add_kernel(int N) {
    int i = blockIdx.x * blockDim.x + threadIdx.x;
    if (i < N) {
        int r = g_rowstart[i] + g_bsum[i / SCAN_B];
        g_rowstart[i] = r;
        g_cursor[i] = r;
    }
}

__global__ void csr_fill_kernel(const int* __restrict__ ei, int E, int N) {
    int e = blockIdx.x * blockDim.x + threadIdx.x;
    if (e < E) {
        int s = ei[e];
        int d = ei[E + e];
        if ((unsigned)s < (unsigned)N && (unsigned)d < (unsigned)N) {
            int pos = atomicAdd(&g_cursor[d], 1);
            g_csrc[pos] = s;
        }
    }
}

// ---------------------------------------------------------------------------
// GEMM1 (tf32 tensor cores + cp.async 3-stage + ldmatrix): g_p1 = dinv ⊙ (A@B)
// block 128x128x16, 8 warps, warp tile 64x32 via mma.m16n8k8.tf32
// A fragments via ldmatrix.m8n8.x4.b16 (bit-moves tf32 words)
// ---------------------------------------------------------------------------
#define G1_BM 128
#define G1_BN 128
#define G1_BK 16
#define G1_KT (F_IN / G1_BK)   // 32 k-tiles
#define STAGES 3
#define AS_STRIDE 20
#define BS_STRIDE 132

__device__ __forceinline__ void mma_tf32(float c[4], const uint32_t a[4],
                                         const uint32_t b[2]) {
    asm volatile(
        "mma.sync.aligned.m16n8k8.row.col.f32.tf32.tf32.f32 "
        "{%0,%1,%2,%3}, {%4,%5,%6,%7}, {%8,%9}, {%0,%1,%2,%3};"
        : "+f"(c[0]), "+f"(c[1]), "+f"(c[2]), "+f"(c[3])
        : "r"(a[0]), "r"(a[1]), "r"(a[2]), "r"(a[3]), "r"(b[0]), "r"(b[1]));
}

__device__ __forceinline__ void cp_async16(uint32_t smem_dst, const void* gsrc,
                                           int src_bytes) {
    asm volatile("cp.async.ca.shared.global [%0], [%1], 16, %2;"
                 :: "r"(smem_dst), "l"(gsrc), "r"(src_bytes));
}

__global__ void __launch_bounds__(256) gemm1_kernel(const float* __restrict__ A,
                                                    const float* __restrict__ B,
                                                    int N) {
    const int K = F_IN, M = H1;
    __shared__ uint32_t As[STAGES][G1_BM * AS_STRIDE];   // 30 KB
    __shared__ uint32_t Bs[STAGES][G1_BK * BS_STRIDE];   // ~25 KB

    int tid = threadIdx.x;
    int lane = tid & 31;
    int w = tid >> 5;
    int wm = w >> 2;
    int wn = w & 3;
    int brow = blockIdx.y * G1_BM;
    int bcol = blockIdx.x * G1_BN;

    int arow = tid >> 1;               // 0..127
    int acg  = (tid & 1) * 4;          // 0 or 4 (plus +8)
    int bk   = tid >> 4;               // 0..15
    int bn   = (tid & 15) * 4;         // 0..60 (plus +64)

    int gr = brow + arow;
    int a_ok = (gr < N) ? 16 : 0;
    const float* a_src0 = &A[(long)gr * K + acg];

    auto load_stage = [&](int st, int k0) {
        uint32_t ad = (uint32_t)__cvta_generic_to_shared(&As[st][arow * AS_STRIDE + acg]);
        cp_async16(ad, a_src0 + k0, a_ok);
        cp_async16(ad + 32, a_src0 + k0 + 8, a_ok);
        uint32_t bd = (uint32_t)__cvta_generic_to_shared(&Bs[st][bk * BS_STRIDE + bn]);
        cp_async16(bd, &B[(long)(k0 + bk) * M + bcol + bn], 16);
        cp_async16(bd + 256, &B[(long)(k0 + bk) * M + bcol + bn + 64], 16);
    };

    // ldmatrix address pieces (constant per thread): matrix m = lane>>3,
    // row-in-matrix = lane&7.  m&1 selects row+8 half, m>>1 selects col+4 half.
    int lm_m   = lane >> 3;
    int lm_row = ((lm_m & 1) << 3) + (lane & 7);   // 0..15
    int lm_col = (lm_m >> 1) << 2;                 // 0 or 4

    float acc[4][4][4];
#pragma unroll
    for (int mi = 0; mi < 4; mi++)
#pragma unroll
        for (int ni = 0; ni < 4; ni++)
#pragma unroll
            for (int q = 0; q < 4; q++) acc[mi][ni][q] = 0.f;

    load_stage(0, 0);
    asm volatile("cp.async.commit_group;");
    load_stage(1, G1_BK);
    asm volatile("cp.async.commit_group;");

    for (int kt = 0; kt < G1_KT; kt++) {
        asm volatile("cp.async.wait_group 1;");
        __syncthreads();

        int buf = kt % STAGES;
        uint32_t as_base = (uint32_t)__cvta_generic_to_shared(&As[buf][0]);
#pragma unroll
        for (int ks = 0; ks < 2; ks++) {
            int kk = ks * 8;
            uint32_t af[4][4], bf[4][2];
#pragma unroll
            for (int mi = 0; mi < 4; mi++) {
                int row = wm * 64 + mi * 16 + lm_row;
                uint32_t addr = as_base + ((row * AS_STRIDE + kk + lm_col) << 2);
                asm volatile(
                    "ldmatrix.sync.aligned.m8n8.x4.shared.b16 {%0,%1,%2,%3}, [%4];"
                    : "=r"(af[mi][0]), "=r"(af[mi][1]),
                      "=r"(af[mi][2]), "=r"(af[mi][3])
                    : "r"(addr));
            }
#pragma unroll
            for (int ni = 0; ni < 4; ni++) {
                int c = wn * 32 + ni * 8 + (lane >> 2);
                int k1 = kk + (lane & 3);
                bf[ni][0] = Bs[buf][k1 * BS_STRIDE + c];
                bf[ni][1] = Bs[buf][(k1 + 4) * BS_STRIDE + c];
            }
#pragma unroll
            for (int mi = 0; mi < 4; mi++)
#pragma unroll
                for (int ni = 0; ni < 4; ni++)
                    mma_tf32(acc[mi][ni], af[mi], bf[ni]);
        }
        // NOTE: no second __syncthreads needed — the stage written below
        // ((kt+2)%3 == (kt-1)%3) was last read at iteration kt-1, and the
        // barrier at the top of this iteration already ordered that.
        if (kt + 2 < G1_KT) load_stage((kt + 2) % STAGES, (kt + 2) * G1_BK);
        asm volatile("cp.async.commit_group;");
    }

    // epilogue: scale by dinv[row], write p1
#pragma unroll
    for (int mi = 0; mi < 4; mi++) {
        int r0 = brow + wm * 64 + mi * 16 + (lane >> 2);
        int r1 = r0 + 8;
        float dv0 = (r0 < N) ? g_dinv[r0] : 0.f;
        float dv1 = (r1 < N) ? g_dinv[r1] : 0.f;
#pragma unroll
        for (int ni = 0; ni < 4; ni++) {
            int c = bcol + wn * 32 + ni * 8 + (lane & 3) * 2;
            if (r0 < N) {
                float2 v = make_float2(dv0 * acc[mi][ni][0], dv0 * acc[mi][ni][1]);
                *(float2*)&g_p1[(long)r0 * M + c] = v;
            }
            if (r1 < N) {
                float2 v = make_float2(dv1 * acc[mi][ni][2], dv1 * acc[mi][ni][3]);
                *(float2*)&g_p1[(long)r1 * M + c] = v;
            }
        }
    }
}

// ---------------------------------------------------------------------------
// gather1 (F=256, float4): a1[d] = relu(dinv[d]*(p1[d]+sum p1[s]) + b1)
// 64 threads per node (float4 each), 4 nodes per 256-thread block
// ---------------------------------------------------------------------------
__global__ void __launch_bounds__(256) gather1_kernel(const float* __restrict__ b1, int N) {
    int tid = threadIdx.x;
    int d = blockIdx.x * 4 + (tid >> 6);
    int f4 = (tid & 63);
    if (d >= N) return;

    const float4* p1v = (const float4*)g_p1;
    long rowbase = (long)d * (H1 / 4);

    int start = g_rowstart[d];
    int deg = g_deg[d];

    float4 acc0 = p1v[rowbase + f4];   // self loop (p1 pre-scaled by dinv[s])
    float4 acc1 = make_float4(0.f, 0.f, 0.f, 0.f);
    int j = 0;
    for (; j + 1 < deg; j += 2) {
        int s0 = __ldg(&g_csrc[start + j]);
        int s1 = __ldg(&g_csrc[start + j + 1]);
        acc0 = f4add(acc0, p1v[(long)s0 * (H1 / 4) + f4]);
        acc1 = f4add(acc1, p1v[(long)s1 * (H1 / 4) + f4]);
    }
    if (j < deg) {
        int s0 = __ldg(&g_csrc[start + j]);
        acc0 = f4add(acc0, p1v[(long)s0 * (H1 / 4) + f4]);
    }

    float dv = g_dinv[d];
    float4 bb = ((const float4*)b1)[f4];
    float4 v = make_float4(dv * (acc0.x + acc1.x) + bb.x,
                           dv * (acc0.y + acc1.y) + bb.y,
                           dv * (acc0.z + acc1.z) + bb.z,
                           dv * (acc0.w + acc1.w) + bb.w);
    v.x = v.x > 0.f ? v.x : 0.f;
    v.y = v.y > 0.f ? v.y : 0.f;
    v.z = v.z > 0.f ? v.z : 0.f;
    v.w = v.w > 0.f ? v.w : 0.f;
    ((float4*)g_a1)[rowbase + f4] = v;
}

// ---------------------------------------------------------------------------
// GEMM2: one thread per node. p2[n] = dinv[n] * (a1[n] @ W2)
// ---------------------------------------------------------------------------
__global__ void __launch_bounds__(256) gemm2_kernel(const float* __restrict__ W, int N) {
    __shared__ float Ws[H1 * H2];      // 16 KB
    int tid = threadIdx.x;
    for (int i = tid; i < H1 * H2; i += 256) Ws[i] = W[i];
    __syncthreads();

    int n = blockIdx.x * 256 + tid;
    if (n >= N) return;

    float acc[H2];
#pragma unroll
    for (int m = 0; m < H2; m++) acc[m] = 0.f;

    const float4* arow = (const float4*)(g_a1 + (long)n * H1);
    for (int k4 = 0; k4 < H1 / 4; k4++) {
        float4 a = arow[k4];
        const float* wk = &Ws[k4 * 4 * H2];
#pragma unroll
        for (int m = 0; m < H2; m++) {
            acc[m] += a.x * wk[m] + a.y * wk[H2 + m] +
                      a.z * wk[2 * H2 + m] + a.w * wk[3 * H2 + m];
        }
    }

    float dv = g_dinv[n];
    float* op = &g_p2[(long)n * H2];
#pragma unroll
    for (int m4 = 0; m4 < 4; m4++) {
        float4 v = make_float4(dv * acc[m4 * 4 + 0], dv * acc[m4 * 4 + 1],
                               dv * acc[m4 * 4 + 2], dv * acc[m4 * 4 + 3]);
        *(float4*)&op[m4 * 4] = v;
    }
}

// ---------------------------------------------------------------------------
// gather2 (F=16, float4): p3[d] = dinv[d]*relu(dinv[d]*(p2[d]+sum p2[s]) + b2)
// ---------------------------------------------------------------------------
__global__ void __launch_bounds__(256) gather2_kernel(const float* __restrict__ b2, int N) {
    int tid = threadIdx.x;
    int d = blockIdx.x * 64 + (tid >> 2);
    int f4 = tid & 3;
    if (d >= N) return;

    const float4* p2v = (const float4*)g_p2;
    int start = g_rowstart[d];
    int deg = g_deg[d];

    float4 acc0 = p2v[(long)d * 4 + f4];
    float4 acc1 = make_float4(0.f, 0.f, 0.f, 0.f);
    int j = 0;
    for (; j + 1 < deg; j += 2) {
        int s0 = __ldg(&g_csrc[start + j]);
        int s1 = __ldg(&g_csrc[start + j + 1]);
        acc0 = f4add(acc0, p2v[(long)s0 * 4 + f4]);
        acc1 = f4add(acc1, p2v[(long)s1 * 4 + f4]);
    }
    if (j < deg) {
        int s0 = __ldg(&g_csrc[start + j]);
        acc0 = f4add(acc0, p2v[(long)s0 * 4 + f4]);
    }

    float dv = g_dinv[d];
    float4 bb = ((const float4*)b2)[f4];
    float4 v = make_float4(dv * (acc0.x + acc1.x) + bb.x,
                           dv * (acc0.y + acc1.y) + bb.y,
                           dv * (acc0.z + acc1.z) + bb.z,
                           dv * (acc0.w + acc1.w) + bb.w);
    v.x = dv * (v.x > 0.f ? v.x : 0.f);
    v.y = dv * (v.y > 0.f ? v.y : 0.f);
    v.z = dv * (v.z > 0.f ? v.z : 0.f);
    v.w = dv * (v.w > 0.f ? v.w : 0.f);
    ((float4*)g_p3)[(long)d * 4 + f4] = v;
}

// ---------------------------------------------------------------------------
// gather3 (F=16, float4): a3[d] = dinv[d]*(p3[d]+sum p3[s])
// ---------------------------------------------------------------------------
__global__ void __launch_bounds__(256) gather3_kernel(int N) {
    int tid = threadIdx.x;
    int d = blockIdx.x * 64 + (tid >> 2);
    int f4 = tid & 3;
    if (d >= N) return;

    const float4* p3v = (const float4*)g_p3;
    int start = g_rowstart[d];
    int deg = g_deg[d];

    float4 acc0 = p3v[(long)d * 4 + f4];
    float4 acc1 = make_float4(0.f, 0.f, 0.f, 0.f);
    int j = 0;
    for (; j + 1 < deg; j += 2) {
        int s0 = __ldg(&g_csrc[start + j]);
        int s1 = __ldg(&g_csrc[start + j + 1]);
        acc0 = f4add(acc0, p3v[(long)s0 * 4 + f4]);
        acc1 = f4add(acc1, p3v[(long)s1 * 4 + f4]);
    }
    if (j < deg) {
        int s0 = __ldg(&g_csrc[start + j]);
        acc0 = f4add(acc0, p3v[(long)s0 * 4 + f4]);
    }

    float dv = g_dinv[d];
    float4 v = make_float4(dv * (acc0.x + acc1.x), dv * (acc0.y + acc1.y),
                           dv * (acc0.z + acc1.z), dv * (acc0.w + acc1.w));
    ((float4*)g_a3)[(long)d * 4 + f4] = v;
}

// ---------------------------------------------------------------------------
// final: o = g_a3 @ W3 + b3 ; log_softmax ; one thread per node
// ---------------------------------------------------------------------------
__global__ void final_kernel(const float* __restrict__ W3,
                             const float* __restrict__ b3,
                             float* __restrict__ out, int N) {
    __shared__ float Ws[H2 * F_OUT];
    __shared__ float bs[F_OUT];
    int tid = threadIdx.x;
    for (int i = tid; i < H2 * F_OUT; i += blockDim.x) Ws[i] = W3[i];
    if (tid < F_OUT) bs[tid] = b3[tid];
    __syncthreads();

    int n = blockIdx.x * blockDim.x + tid;
    if (n >= N) return;

    float a[H2];
    const float4* ap = (const float4*)(g_a3 + (long)n * H2);
#pragma unroll
    for (int i = 0; i < 4; i++) {
        float4 v = ap[i];
        a[i * 4 + 0] = v.x; a[i * 4 + 1] = v.y;
        a[i * 4 + 2] = v.z; a[i * 4 + 3] = v.w;
    }

    float o[F_OUT];
#pragma unroll
    for (int m = 0; m < F_OUT; m++) {
        float acc = bs[m];
#pragma unroll
        for (int k = 0; k < H2; k++) acc += a[k] * Ws[k * F_OUT + m];
        o[m] = acc;
    }

    float mx = o[0];
#pragma unroll
    for (int m = 1; m < F_OUT; m++) mx = fmaxf(mx, o[m]);
    float sum = 0.f;
#pragma unroll
    for (int m = 0; m < F_OUT; m++) sum += __expf(o[m] - mx);
    float lse = mx + __logf(sum);

    float* op = out + (long)n * F_OUT;
#pragma unroll
    for (int m = 0; m < F_OUT; m++) op[m] = o[m] - lse;
}

// ---------------------------------------------------------------------------
// host launcher — kernel launches only (gemm1 kept at launch position 4
// so the ncu capture window lands on it)
// ---------------------------------------------------------------------------
extern "C" void kernel_launch(void* const* d_in, const int* in_sizes, int n_in,
                              void* d_out, int out_size) {
    const float* x  = (const float*)d_in[0];
    const int*   ei = (const int*)d_in[1];      // int64 delivered as int32
    const float* W1 = (const float*)d_in[2];
    const float* b1 = (const float*)d_in[3];
    const float* W2 = (const float*)d_in[4];
    const float* b2 = (const float*)d_in[5];
    const float* W3 = (const float*)d_in[6];
    const float* b3 = (const float*)d_in[7];
    float* out = (float*)d_out;

    int N = in_sizes[0] / F_IN;
    int E = in_sizes[1] / 2;
    int nblk = (N + SCAN_B - 1) / SCAN_B;

    // 1-3: degree + dinv (gemm1 epilogue needs dinv)
    zero_deg_kernel<<<(N + 255) / 256, 256>>>(N);
    count_deg_kernel<<<(E + 255) / 256, 256>>>(ei, E, N);
    dinv_kernel<<<(N + 255) / 256, 256>>>(N);

    // 4: layer 1 GEMM (tf32 + cp.async pipeline + ldmatrix, dinv fused)
    {
        dim3 grid(H1 / G1_BN, (N + G1_BM - 1) / G1_BM);
        gemm1_kernel<<<grid, 256>>>(x, W1, N);
    }

    // 5-8: CSR build
    scan_partial_kernel<<<nblk, SCAN_B>>>(N);
    scan_bsum_kernel<<<1, SCAN_B>>>(nblk);
    scan_add_kernel<<<(N + 255) / 256, 256>>>(N);
    csr_fill_kernel<<<(E + 255) / 256, 256>>>(ei, E, N);

    // 9: layer 1 aggregation (+bias/relu)
    gather1_kernel<<<(N + 3) / 4, 256>>>(b1, N);

    // 10-11: layer 2
    gemm2_kernel<<<(N + 255) / 256, 256>>>(W2, N);
    gather2_kernel<<<(N + 63) / 64, 256>>>(b2, N);

    // 12-13: layer 3 aggregation + head
    gather3_kernel<<<(N + 63) / 64, 256>>>(N);
    final_kernel<<<(N + 255) / 256, 256>>>(W3, b3, out, N);
}

// round 11
// speedup vs baseline: 1.6495x; 1.0781x over previous
#include <cuda_runtime.h>
#include <cuda_fp16.h>
#include <math.h>
#include <stdint.h>

// Problem constants (fixed for this problem instance)
#define NMAX   50000
#define EMAX   800000
#define F_IN   512
#define H1     256
#define H2     16
#define F_OUT  40

#define SCAN_B 256

// Scratch (static device arrays; no allocation allowed)
__device__ __half g_p1h[NMAX * H1]; // dinv ⊙ (x @ W1), fp16
__device__ float g_a1[NMAX * H1];   // relu(Ahat h1 + b1)
__device__ float g_p2[NMAX * H2];   // dinv ⊙ (a1 @ W2)
__device__ float g_p3[NMAX * H2];   // dinv ⊙ relu(Ahat h2 + b2)
__device__ float g_a3[NMAX * H2];   // Ahat r2
__device__ int   g_deg[NMAX];       // edge-only in-degree (no self loop)
__device__ int   g_rowstart[NMAX];
__device__ int   g_cursor[NMAX];
__device__ int   g_csrc[EMAX];      // src indices grouped by dst (CSR)
__device__ int   g_bsum[SCAN_B];
__device__ float g_dinv[NMAX];

__device__ __forceinline__ float4 f4add(float4 a, float4 b) {
    return make_float4(a.x + b.x, a.y + b.y, a.z + b.z, a.w + b.w);
}

// unpack 8 halves (uint4) and accumulate into 8 fp32 accumulators
__device__ __forceinline__ void h8add(float acc[8], uint4 v) {
    const __half2* h = (const __half2*)&v;
#pragma unroll
    for (int i = 0; i < 4; i++) {
        float2 f = __half22float2(h[i]);
        acc[2 * i]     += f.x;
        acc[2 * i + 1] += f.y;
    }
}

// ---------------------------------------------------------------------------
// degree / dinv / scan / CSR fill
// ---------------------------------------------------------------------------
__global__ void zero_deg_kernel(int N) {
    int i = blockIdx.x * blockDim.x + threadIdx.x;
    if (i < N) g_deg[i] = 0;
}

__global__ void count_deg_kernel(const int* __restrict__ ei, int E, int N) {
    int e = blockIdx.x * blockDim.x + threadIdx.x;
    if (e < E) {
        int d = ei[E + e];
        if ((unsigned)d < (unsigned)N) atomicAdd(&g_deg[d], 1);
    }
}

__global__ void dinv_kernel(int N) {
    int i = blockIdx.x * blockDim.x + threadIdx.x;
    if (i < N) g_dinv[i] = rsqrtf((float)(g_deg[i] + 1));   // +1 self-loop
}

__global__ void scan_partial_kernel(int N) {
    __shared__ int sd[SCAN_B];
    int t = threadIdx.x, b = blockIdx.x;
    int i = b * SCAN_B + t;
    int v = (i < N) ? g_deg[i] : 0;
    sd[t] = v;
    __syncthreads();
#pragma unroll
    for (int off = 1; off < SCAN_B; off <<= 1) {
        int x = (t >= off) ? sd[t - off] : 0;
        __syncthreads();
        sd[t] += x;
        __syncthreads();
    }
    if (i < N) g_rowstart[i] = sd[t] - v;       // exclusive
    if (t == SCAN_B - 1) g_bsum[b] = sd[t];
}

__global__ void scan_bsum_kernel(int nblk) {
    __shared__ int sd[SCAN_B];
    int t = threadIdx.x;
    int v = (t < nblk) ? g_bsum[t] : 0;
    sd[t] = v;
    __syncthreads();
#pragma unroll
    for (int off = 1; off < SCAN_B; off <<= 1) {
        int x = (t >= off) ? sd[t - off] : 0;
        __syncthreads();
        sd[t] += x;
        __syncthreads();
    }
    if (t < nblk) g_bsum[t] = sd[t] - v;
}

__global__ void scan_add_kernel(int N) {
    int i = blockIdx.x * blockDim.x + threadIdx.x;
    if (i < N) {
        int r = g_rowstart[i] + g_bsum[i / SCAN_B];
        g_rowstart[i] = r;
        g_cursor[i] = r;
    }
}

__global__ void csr_fill_kernel(const int* __restrict__ ei, int E, int N) {
    int e = blockIdx.x * blockDim.x + threadIdx.x;
    if (e < E) {
        int s = ei[e];
        int d = ei[E + e];
        if ((unsigned)s < (unsigned)N && (unsigned)d < (unsigned)N) {
            int pos = atomicAdd(&g_cursor[d], 1);
            g_csrc[pos] = s;
        }
    }
}

// ---------------------------------------------------------------------------
// GEMM1 (tf32 tensor cores + cp.async 3-stage + ldmatrix): g_p1h = dinv ⊙ (A@B)
// block 128x128x16, 8 warps, warp tile 64x32 via mma.m16n8k8.tf32
// epilogue emits fp16
// ---------------------------------------------------------------------------
#define G1_BM 128
#define G1_BN 128
#define G1_BK 16
#define G1_KT (F_IN / G1_BK)   // 32 k-tiles
#define STAGES 3
#define AS_STRIDE 20
#define BS_STRIDE 132

__device__ __forceinline__ void mma_tf32(float c[4], const uint32_t a[4],
                                         const uint32_t b[2]) {
    asm volatile(
        "mma.sync.aligned.m16n8k8.row.col.f32.tf32.tf32.f32 "
        "{%0,%1,%2,%3}, {%4,%5,%6,%7}, {%8,%9}, {%0,%1,%2,%3};"
        : "+f"(c[0]), "+f"(c[1]), "+f"(c[2]), "+f"(c[3])
        : "r"(a[0]), "r"(a[1]), "r"(a[2]), "r"(a[3]), "r"(b[0]), "r"(b[1]));
}

__device__ __forceinline__ void cp_async16(uint32_t smem_dst, const void* gsrc,
                                           int src_bytes) {
    asm volatile("cp.async.ca.shared.global [%0], [%1], 16, %2;"
                 :: "r"(smem_dst), "l"(gsrc), "r"(src_bytes));
}

__global__ void __launch_bounds__(256) gemm1_kernel(const float* __restrict__ A,
                                                    const float* __restrict__ B,
                                                    int N) {
    const int K = F_IN, M = H1;
    __shared__ uint32_t As[STAGES][G1_BM * AS_STRIDE];   // 30 KB
    __shared__ uint32_t Bs[STAGES][G1_BK * BS_STRIDE];   // ~25 KB

    int tid = threadIdx.x;
    int lane = tid & 31;
    int w = tid >> 5;
    int wm = w >> 2;
    int wn = w & 3;
    int brow = blockIdx.y * G1_BM;
    int bcol = blockIdx.x * G1_BN;

    int arow = tid >> 1;               // 0..127
    int acg  = (tid & 1) * 4;          // 0 or 4 (plus +8)
    int bk   = tid >> 4;               // 0..15
    int bn   = (tid & 15) * 4;         // 0..60 (plus +64)

    int gr = brow + arow;
    int a_ok = (gr < N) ? 16 : 0;
    const float* a_src0 = &A[(long)gr * K + acg];

    auto load_stage = [&](int st, int k0) {
        uint32_t ad = (uint32_t)__cvta_generic_to_shared(&As[st][arow * AS_STRIDE + acg]);
        cp_async16(ad, a_src0 + k0, a_ok);
        cp_async16(ad + 32, a_src0 + k0 + 8, a_ok);
        uint32_t bd = (uint32_t)__cvta_generic_to_shared(&Bs[st][bk * BS_STRIDE + bn]);
        cp_async16(bd, &B[(long)(k0 + bk) * M + bcol + bn], 16);
        cp_async16(bd + 256, &B[(long)(k0 + bk) * M + bcol + bn + 64], 16);
    };

    int lm_m   = lane >> 3;
    int lm_row = ((lm_m & 1) << 3) + (lane & 7);   // 0..15
    int lm_col = (lm_m >> 1) << 2;                 // 0 or 4

    float acc[4][4][4];
#pragma unroll
    for (int mi = 0; mi < 4; mi++)
#pragma unroll
        for (int ni = 0; ni < 4; ni++)
#pragma unroll
            for (int q = 0; q < 4; q++) acc[mi][ni][q] = 0.f;

    load_stage(0, 0);
    asm volatile("cp.async.commit_group;");
    load_stage(1, G1_BK);
    asm volatile("cp.async.commit_group;");

    for (int kt = 0; kt < G1_KT; kt++) {
        asm volatile("cp.async.wait_group 1;");
        __syncthreads();

        int buf = kt % STAGES;
        uint32_t as_base = (uint32_t)__cvta_generic_to_shared(&As[buf][0]);
#pragma unroll
        for (int ks = 0; ks < 2; ks++) {
            int kk = ks * 8;
            uint32_t af[4][4], bf[4][2];
#pragma unroll
            for (int mi = 0; mi < 4; mi++) {
                int row = wm * 64 + mi * 16 + lm_row;
                uint32_t addr = as_base + ((row * AS_STRIDE + kk + lm_col) << 2);
                asm volatile(
                    "ldmatrix.sync.aligned.m8n8.x4.shared.b16 {%0,%1,%2,%3}, [%4];"
                    : "=r"(af[mi][0]), "=r"(af[mi][1]),
                      "=r"(af[mi][2]), "=r"(af[mi][3])
                    : "r"(addr));
            }
#pragma unroll
            for (int ni = 0; ni < 4; ni++) {
                int c = wn * 32 + ni * 8 + (lane >> 2);
                int k1 = kk + (lane & 3);
                bf[ni][0] = Bs[buf][k1 * BS_STRIDE + c];
                bf[ni][1] = Bs[buf][(k1 + 4) * BS_STRIDE + c];
            }
#pragma unroll
            for (int mi = 0; mi < 4; mi++)
#pragma unroll
                for (int ni = 0; ni < 4; ni++)
                    mma_tf32(acc[mi][ni], af[mi], bf[ni]);
        }
        // stage written below was last read at kt-1; top-of-loop barrier ordered it
        if (kt + 2 < G1_KT) load_stage((kt + 2) % STAGES, (kt + 2) * G1_BK);
        asm volatile("cp.async.commit_group;");
    }

    // epilogue: scale by dinv[row], write p1 as fp16 (half2 stores)
#pragma unroll
    for (int mi = 0; mi < 4; mi++) {
        int r0 = brow + wm * 64 + mi * 16 + (lane >> 2);
        int r1 = r0 + 8;
        float dv0 = (r0 < N) ? g_dinv[r0] : 0.f;
        float dv1 = (r1 < N) ? g_dinv[r1] : 0.f;
#pragma unroll
        for (int ni = 0; ni < 4; ni++) {
            int c = bcol + wn * 32 + ni * 8 + (lane & 3) * 2;
            if (r0 < N) {
                __half2 v = __floats2half2_rn(dv0 * acc[mi][ni][0],
                                              dv0 * acc[mi][ni][1]);
                *(__half2*)&g_p1h[(long)r0 * M + c] = v;
            }
            if (r1 < N) {
                __half2 v = __floats2half2_rn(dv1 * acc[mi][ni][2],
                                              dv1 * acc[mi][ni][3]);
                *(__half2*)&g_p1h[(long)r1 * M + c] = v;
            }
        }
    }
}

// ---------------------------------------------------------------------------
// gather1 (F=256, fp16 src): a1[d] = relu(dinv[d]*(p1[d]+sum p1[s]) + b1)
// 32 threads per node (uint4 = 8 halves each), 8 nodes per 256-thread block
// ---------------------------------------------------------------------------
__global__ void __launch_bounds__(256) gather1_kernel(const float* __restrict__ b1, int N) {
    int tid = threadIdx.x;
    int d = blockIdx.x * 8 + (tid >> 5);
    int lane = tid & 31;
    if (d >= N) return;

    const uint4* p1v = (const uint4*)g_p1h;    // 8 halves per uint4; 32/row
    long rowbase = (long)d * 32;

    int start = g_rowstart[d];
    int deg = g_deg[d];

    float acc0[8], acc1[8];
    {
        uint4 v = p1v[rowbase + lane];         // self loop (pre-scaled)
        const __half2* h = (const __half2*)&v;
#pragma unroll
        for (int i = 0; i < 4; i++) {
            float2 f = __half22float2(h[i]);
            acc0[2 * i] = f.x; acc0[2 * i + 1] = f.y;
            acc1[2 * i] = 0.f; acc1[2 * i + 1] = 0.f;
        }
    }

    int j = 0;
    for (; j + 1 < deg; j += 2) {
        int s0 = __ldg(&g_csrc[start + j]);
        int s1 = __ldg(&g_csrc[start + j + 1]);
        uint4 v0 = p1v[(long)s0 * 32 + lane];
        uint4 v1 = p1v[(long)s1 * 32 + lane];
        h8add(acc0, v0);
        h8add(acc1, v1);
    }
    if (j < deg) {
        int s0 = __ldg(&g_csrc[start + j]);
        h8add(acc0, p1v[(long)s0 * 32 + lane]);
    }

    float dv = g_dinv[d];
    float4 ba = *(const float4*)&b1[lane * 8];
    float4 bb = *(const float4*)&b1[lane * 8 + 4];
    float o[8];
#pragma unroll
    for (int i = 0; i < 8; i++) o[i] = dv * (acc0[i] + acc1[i]);
    o[0] += ba.x; o[1] += ba.y; o[2] += ba.z; o[3] += ba.w;
    o[4] += bb.x; o[5] += bb.y; o[6] += bb.z; o[7] += bb.w;
#pragma unroll
    for (int i = 0; i < 8; i++) o[i] = o[i] > 0.f ? o[i] : 0.f;

    float* op = &g_a1[(long)d * H1 + lane * 8];
    *(float4*)&op[0] = make_float4(o[0], o[1], o[2], o[3]);
    *(float4*)&op[4] = make_float4(o[4], o[5], o[6], o[7]);
}

// ---------------------------------------------------------------------------
// GEMM2: one thread per node. p2[n] = dinv[n] * (a1[n] @ W2)
// ---------------------------------------------------------------------------
__global__ void __launch_bounds__(256) gemm2_kernel(const float* __restrict__ W, int N) {
    __shared__ float Ws[H1 * H2];      // 16 KB
    int tid = threadIdx.x;
    for (int i = tid; i < H1 * H2; i += 256) Ws[i] = W[i];
    __syncthreads();

    int n = blockIdx.x * 256 + tid;
    if (n >= N) return;

    float acc[H2];
#pragma unroll
    for (int m = 0; m < H2; m++) acc[m] = 0.f;

    const float4* arow = (const float4*)(g_a1 + (long)n * H1);
    for (int k4 = 0; k4 < H1 / 4; k4++) {
        float4 a = arow[k4];
        const float* wk = &Ws[k4 * 4 * H2];
#pragma unroll
        for (int m = 0; m < H2; m++) {
            acc[m] += a.x * wk[m] + a.y * wk[H2 + m] +
                      a.z * wk[2 * H2 + m] + a.w * wk[3 * H2 + m];
        }
    }

    float dv = g_dinv[n];
    float* op = &g_p2[(long)n * H2];
#pragma unroll
    for (int m4 = 0; m4 < 4; m4++) {
        float4 v = make_float4(dv * acc[m4 * 4 + 0], dv * acc[m4 * 4 + 1],
                               dv * acc[m4 * 4 + 2], dv * acc[m4 * 4 + 3]);
        *(float4*)&op[m4 * 4] = v;
    }
}

// ---------------------------------------------------------------------------
// gather2 (F=16, float4): p3[d] = dinv[d]*relu(dinv[d]*(p2[d]+sum p2[s]) + b2)
// ---------------------------------------------------------------------------
__global__ void __launch_bounds__(256) gather2_kernel(const float* __restrict__ b2, int N) {
    int tid = threadIdx.x;
    int d = blockIdx.x * 64 + (tid >> 2);
    int f4 = tid & 3;
    if (d >= N) return;

    const float4* p2v = (const float4*)g_p2;
    int start = g_rowstart[d];
    int deg = g_deg[d];

    float4 acc0 = p2v[(long)d * 4 + f4];
    float4 acc1 = make_float4(0.f, 0.f, 0.f, 0.f);
    int j = 0;
    for (; j + 1 < deg; j += 2) {
        int s0 = __ldg(&g_csrc[start + j]);
        int s1 = __ldg(&g_csrc[start + j + 1]);
        acc0 = f4add(acc0, p2v[(long)s0 * 4 + f4]);
        acc1 = f4add(acc1, p2v[(long)s1 * 4 + f4]);
    }
    if (j < deg) {
        int s0 = __ldg(&g_csrc[start + j]);
        acc0 = f4add(acc0, p2v[(long)s0 * 4 + f4]);
    }

    float dv = g_dinv[d];
    float4 bb = ((const float4*)b2)[f4];
    float4 v = make_float4(dv * (acc0.x + acc1.x) + bb.x,
                           dv * (acc0.y + acc1.y) + bb.y,
                           dv * (acc0.z + acc1.z) + bb.z,
                           dv * (acc0.w + acc1.w) + bb.w);
    v.x = dv * (v.x > 0.f ? v.x : 0.f);
    v.y = dv * (v.y > 0.f ? v.y : 0.f);
    v.z = dv * (v.z > 0.f ? v.z : 0.f);
    v.w = dv * (v.w > 0.f ? v.w : 0.f);
    ((float4*)g_p3)[(long)d * 4 + f4] = v;
}

// ---------------------------------------------------------------------------
// gather3 (F=16, float4): a3[d] = dinv[d]*(p3[d]+sum p3[s])
// ---------------------------------------------------------------------------
__global__ void __launch_bounds__(256) gather3_kernel(int N) {
    int tid = threadIdx.x;
    int d = blockIdx.x * 64 + (tid >> 2);
    int f4 = tid & 3;
    if (d >= N) return;

    const float4* p3v = (const float4*)g_p3;
    int start = g_rowstart[d];
    int deg = g_deg[d];

    float4 acc0 = p3v[(long)d * 4 + f4];
    float4 acc1 = make_float4(0.f, 0.f, 0.f, 0.f);
    int j = 0;
    for (; j + 1 < deg; j += 2) {
        int s0 = __ldg(&g_csrc[start + j]);
        int s1 = __ldg(&g_csrc[start + j + 1]);
        acc0 = f4add(acc0, p3v[(long)s0 * 4 + f4]);
        acc1 = f4add(acc1, p3v[(long)s1 * 4 + f4]);
    }
    if (j < deg) {
        int s0 = __ldg(&g_csrc[start + j]);
        acc0 = f4add(acc0, p3v[(long)s0 * 4 + f4]);
    }

    float dv = g_dinv[d];
    float4 v = make_float4(dv * (acc0.x + acc1.x), dv * (acc0.y + acc1.y),
                           dv * (acc0.z + acc1.z), dv * (acc0.w + acc1.w));
    ((float4*)g_a3)[(long)d * 4 + f4] = v;
}

// ---------------------------------------------------------------------------
// final: o = g_a3 @ W3 + b3 ; log_softmax ; one thread per node
// ---------------------------------------------------------------------------
__global__ void final_kernel(const float* __restrict__ W3,
                             const float* __restrict__ b3,
                             float* __restrict__ out, int N) {
    __shared__ float Ws[H2 * F_OUT];
    __shared__ float bs[F_OUT];
    int tid = threadIdx.x;
    for (int i = tid; i < H2 * F_OUT; i += blockDim.x) Ws[i] = W3[i];
    if (tid < F_OUT) bs[tid] = b3[tid];
    __syncthreads();

    int n = blockIdx.x * blockDim.x + tid;
    if (n >= N) return;

    float a[H2];
    const float4* ap = (const float4*)(g_a3 + (long)n * H2);
#pragma unroll
    for (int i = 0; i < 4; i++) {
        float4 v = ap[i];
        a[i * 4 + 0] = v.x; a[i * 4 + 1] = v.y;
        a[i * 4 + 2] = v.z; a[i * 4 + 3] = v.w;
    }

    float o[F_OUT];
#pragma unroll
    for (int m = 0; m < F_OUT; m++) {
        float acc = bs[m];
#pragma unroll
        for (int k = 0; k < H2; k++) acc += a[k] * Ws[k * F_OUT + m];
        o[m] = acc;
    }

    float mx = o[0];
#pragma unroll
    for (int m = 1; m < F_OUT; m++) mx = fmaxf(mx, o[m]);
    float sum = 0.f;
#pragma unroll
    for (int m = 0; m < F_OUT; m++) sum += __expf(o[m] - mx);
    float lse = mx + __logf(sum);

    float* op = out + (long)n * F_OUT;
#pragma unroll
    for (int m = 0; m < F_OUT; m++) op[m] = o[m] - lse;
}

// ---------------------------------------------------------------------------
// host launcher — kernel launches only (gemm1 kept at launch position 4)
// ---------------------------------------------------------------------------
extern "C" void kernel_launch(void* const* d_in, const int* in_sizes, int n_in,
                              void* d_out, int out_size) {
    const float* x  = (const float*)d_in[0];
    const int*   ei = (const int*)d_in[1];      // int64 delivered as int32
    const float* W1 = (const float*)d_in[2];
    const float* b1 = (const float*)d_in[3];
    const float* W2 = (const float*)d_in[4];
    const float* b2 = (const float*)d_in[5];
    const float* W3 = (const float*)d_in[6];
    const float* b3 = (const float*)d_in[7];
    float* out = (float*)d_out;

    int N = in_sizes[0] / F_IN;
    int E = in_sizes[1] / 2;
    int nblk = (N + SCAN_B - 1) / SCAN_B;

    // 1-3: degree + dinv (gemm1 epilogue needs dinv)
    zero_deg_kernel<<<(N + 255) / 256, 256>>>(N);
    count_deg_kernel<<<(E + 255) / 256, 256>>>(ei, E, N);
    dinv_kernel<<<(N + 255) / 256, 256>>>(N);

    // 4: layer 1 GEMM (tf32 + cp.async + ldmatrix, dinv fused, fp16 out)
    {
        dim3 grid(H1 / G1_BN, (N + G1_BM - 1) / G1_BM);
        gemm1_kernel<<<grid, 256>>>(x, W1, N);
    }

    // 5-8: CSR build
    scan_partial_kernel<<<nblk, SCAN_B>>>(N);
    scan_bsum_kernel<<<1, SCAN_B>>>(nblk);
    scan_add_kernel<<<(N + 255) / 256, 256>>>(N);
    csr_fill_kernel<<<(E + 255) / 256, 256>>>(ei, E, N);

    // 9: layer 1 aggregation (+bias/relu), fp16 gather
    gather1_kernel<<<(N + 7) / 8, 256>>>(b1, N);

    // 10-11: layer 2
    gemm2_kernel<<<(N + 255) / 256, 256>>>(W2, N);
    gather2_kernel<<<(N + 63) / 64, 256>>>(b2, N);

    // 12-13: layer 3 aggregation + head
    gather3_kernel<<<(N + 63) / 64, 256>>>(N);
    final_kernel<<<(N + 255) / 256, 256>>>(W3, b3, out, N);
}

// round 12
// speedup vs baseline: 1.8351x; 1.1125x over previous
#include <cuda_runtime.h>
#include <cuda_fp16.h>
#include <math.h>
#include <stdint.h>

// Problem constants (fixed for this problem instance)
#define NMAX   50000
#define EMAX   800000
#define F_IN   512
#define H1     256
#define H2     16
#define F_OUT  40

#define SCAN_B 256

// Scratch (static device arrays; no allocation allowed)
__device__ __half g_xh[NMAX * F_IN];  // x in fp16
__device__ __half g_w1t[H1 * F_IN];   // W1 transposed [m][k], fp16
__device__ __half g_p1h[NMAX * H1];   // dinv ⊙ (x @ W1), fp16
__device__ float g_a1[NMAX * H1];     // relu(Ahat h1 + b1)
__device__ float g_p2[NMAX * H2];     // dinv ⊙ (a1 @ W2)
__device__ float g_p3[NMAX * H2];     // dinv ⊙ relu(Ahat h2 + b2)
__device__ float g_a3[NMAX * H2];     // Ahat r2
__device__ int   g_deg[NMAX];
__device__ int   g_rowstart[NMAX];
__device__ int   g_cursor[NMAX];
__device__ int   g_csrc[EMAX];
__device__ int   g_bsum[SCAN_B];
__device__ float g_dinv[NMAX];

__device__ __forceinline__ float4 f4add(float4 a, float4 b) {
    return make_float4(a.x + b.x, a.y + b.y, a.z + b.z, a.w + b.w);
}

__device__ __forceinline__ void h8add(float acc[8], uint4 v) {
    const __half2* h = (const __half2*)&v;
#pragma unroll
    for (int i = 0; i < 4; i++) {
        float2 f = __half22float2(h[i]);
        acc[2 * i]     += f.x;
        acc[2 * i + 1] += f.y;
    }
}

// ---------------------------------------------------------------------------
// conversions
// ---------------------------------------------------------------------------
__global__ void convert_x_kernel(const float* __restrict__ x, long total8) {
    long i = (long)blockIdx.x * blockDim.x + threadIdx.x;
    if (i < total8) {
        float4 a = ((const float4*)x)[2 * i];
        float4 b = ((const float4*)x)[2 * i + 1];
        uint4 v;
        ((__half2*)&v)[0] = __floats2half2_rn(a.x, a.y);
        ((__half2*)&v)[1] = __floats2half2_rn(a.z, a.w);
        ((__half2*)&v)[2] = __floats2half2_rn(b.x, b.y);
        ((__half2*)&v)[3] = __floats2half2_rn(b.z, b.w);
        ((uint4*)g_xh)[i] = v;
    }
}

__global__ void convert_w1t_kernel(const float* __restrict__ W1) {
    int i = blockIdx.x * blockDim.x + threadIdx.x;   // over H1*F_IN
    if (i < H1 * F_IN) {
        int m = i >> 9;          // /512
        int k = i & 511;
        g_w1t[i] = __float2half_rn(W1[k * H1 + m]);
    }
}

// ---------------------------------------------------------------------------
// degree / dinv / scan / CSR fill
// ---------------------------------------------------------------------------
__global__ void zero_deg_kernel(int N) {
    int i = blockIdx.x * blockDim.x + threadIdx.x;
    if (i < N) g_deg[i] = 0;
}

__global__ void count_deg_kernel(const int* __restrict__ ei, int E, int N) {
    int e = blockIdx.x * blockDim.x + threadIdx.x;
    if (e < E) {
        int d = ei[E + e];
        if ((unsigned)d < (unsigned)N) atomicAdd(&g_deg[d], 1);
    }
}

__global__ void dinv_kernel(int N) {
    int i = blockIdx.x * blockDim.x + threadIdx.x;
    if (i < N) g_dinv[i] = rsqrtf((float)(g_deg[i] + 1));   // +1 self-loop
}

__global__ void scan_partial_kernel(int N) {
    __shared__ int sd[SCAN_B];
    int t = threadIdx.x, b = blockIdx.x;
    int i = b * SCAN_B + t;
    int v = (i < N) ? g_deg[i] : 0;
    sd[t] = v;
    __syncthreads();
#pragma unroll
    for (int off = 1; off < SCAN_B; off <<= 1) {
        int x = (t >= off) ? sd[t - off] : 0;
        __syncthreads();
        sd[t] += x;
        __syncthreads();
    }
    if (i < N) g_rowstart[i] = sd[t] - v;       // exclusive
    if (t == SCAN_B - 1) g_bsum[b] = sd[t];
}

__global__ void scan_bsum_kernel(int nblk) {
    __shared__ int sd[SCAN_B];
    int t = threadIdx.x;
    int v = (t < nblk) ? g_bsum[t] : 0;
    sd[t] = v;
    __syncthreads();
#pragma unroll
    for (int off = 1; off < SCAN_B; off <<= 1) {
        int x = (t >= off) ? sd[t - off] : 0;
        __syncthreads();
        sd[t] += x;
        __syncthreads();
    }
    if (t < nblk) g_bsum[t] = sd[t] - v;
}

__global__ void scan_add_kernel(int N) {
    int i = blockIdx.x * blockDim.x + threadIdx.x;
    if (i < N) {
        int r = g_rowstart[i] + g_bsum[i / SCAN_B];
        g_rowstart[i] = r;
        g_cursor[i] = r;
    }
}

__global__ void csr_fill_kernel(const int* __restrict__ ei, int E, int N) {
    int e = blockIdx.x * blockDim.x + threadIdx.x;
    if (e < E) {
        int s = ei[e];
        int d = ei[E + e];
        if ((unsigned)s < (unsigned)N && (unsigned)d < (unsigned)N) {
            int pos = atomicAdd(&g_cursor[d], 1);
            g_csrc[pos] = s;
        }
    }
}

// ---------------------------------------------------------------------------
// GEMM1 (fp16 tensor cores, mma.m16n8k16, fp32 accum, cp.async 3-stage,
// ldmatrix for A and B): g_p1h = dinv ⊙ (xh @ W1)
// block 128x128, BK=32 halves, 8 warps, warp tile 64x32
// A smem [row][k] 128x(32+8), B smem [n][k] 128x(32+8) from g_w1t
// ---------------------------------------------------------------------------
#define G1_BM 128
#define G1_BN 128
#define G1_BK 32
#define G1_KT (F_IN / G1_BK)   // 16 k-tiles
#define STAGES 3
#define HS_STRIDE 40           // halves; 80B rows, conflict-free ldmatrix

__device__ __forceinline__ void mma_f16(float c[4], const uint32_t a[4],
                                        const uint32_t b[2]) {
    asm volatile(
        "mma.sync.aligned.m16n8k16.row.col.f32.f16.f16.f32 "
        "{%0,%1,%2,%3}, {%4,%5,%6,%7}, {%8,%9}, {%0,%1,%2,%3};"
        : "+f"(c[0]), "+f"(c[1]), "+f"(c[2]), "+f"(c[3])
        : "r"(a[0]), "r"(a[1]), "r"(a[2]), "r"(a[3]), "r"(b[0]), "r"(b[1]));
}

__device__ __forceinline__ void cp_async16(uint32_t smem_dst, const void* gsrc,
                                           int src_bytes) {
    asm volatile("cp.async.ca.shared.global [%0], [%1], 16, %2;"
                 :: "r"(smem_dst), "l"(gsrc), "r"(src_bytes));
}

__global__ void __launch_bounds__(256) gemm1_kernel(int N) {
    const int M = H1;
    __shared__ __half As[STAGES][G1_BM * HS_STRIDE];   // 30 KB
    __shared__ __half Bs[STAGES][G1_BN * HS_STRIDE];   // 30 KB

    int tid = threadIdx.x;
    int lane = tid & 31;
    int w = tid >> 5;
    int wm = w >> 2;          // 0..1
    int wn = w & 3;           // 0..3
    int brow = blockIdx.y * G1_BM;
    int bcol = blockIdx.x * G1_BN;

    // load mapping: 128 rows x 32 halves (64B) = 4 chunks of 16B per row
    // 256 threads: thread covers row tid>>1, chunks 2*(tid&1), 2*(tid&1)+1
    int ldrow = tid >> 1;
    int ldoff = (tid & 1) * 16;        // half offset (16 or 0), chunk pair

    int gr = brow + ldrow;
    int a_ok = (gr < N) ? 16 : 0;
    const __half* a_src0 = &g_xh[(long)gr * F_IN + ldoff];
    const __half* b_src0 = &g_w1t[(long)(bcol + ldrow) * F_IN + ldoff];

    auto load_stage = [&](int st, int k0) {
        uint32_t ad = (uint32_t)__cvta_generic_to_shared(
            &As[st][ldrow * HS_STRIDE + ldoff]);
        cp_async16(ad, a_src0 + k0, a_ok);
        cp_async16(ad + 16, a_src0 + k0 + 8, a_ok);
        uint32_t bd = (uint32_t)__cvta_generic_to_shared(
            &Bs[st][ldrow * HS_STRIDE + ldoff]);
        cp_async16(bd, b_src0 + k0, 16);
        cp_async16(bd + 16, b_src0 + k0 + 8, 16);
    };

    // ldmatrix thread-address pieces
    int lm_m = lane >> 3;                          // matrix index 0..3
    int a_row = ((lm_m & 1) << 3) + (lane & 7);    // A: row-in-16 (0..15)
    int a_kof = (lm_m >> 1) << 3;                  // A: k offset 0/8
    int b_nof = ((lane >> 4) & 1) << 3;            // B: n offset 0/8
    int b_row = b_nof + (lane & 7);                // B: n-in-16
    int b_kof = ((lane >> 3) & 1) << 3;            // B: k offset 0/8

    float acc[4][4][4];
#pragma unroll
    for (int mi = 0; mi < 4; mi++)
#pragma unroll
        for (int ni = 0; ni < 4; ni++)
#pragma unroll
            for (int q = 0; q < 4; q++) acc[mi][ni][q] = 0.f;

    load_stage(0, 0);
    asm volatile("cp.async.commit_group;");
    load_stage(1, G1_BK);
    asm volatile("cp.async.commit_group;");

    for (int kt = 0; kt < G1_KT; kt++) {
        asm volatile("cp.async.wait_group 1;");
        __syncthreads();

        int buf = kt % STAGES;
        uint32_t as_base = (uint32_t)__cvta_generic_to_shared(&As[buf][0]);
        uint32_t bs_base = (uint32_t)__cvta_generic_to_shared(&Bs[buf][0]);
#pragma unroll
        for (int ks = 0; ks < 2; ks++) {
            int kk = ks * 16;
            uint32_t af[4][4], bf[4][2];
#pragma unroll
            for (int mi = 0; mi < 4; mi++) {
                int row = wm * 64 + mi * 16 + a_row;
                uint32_t addr = as_base + ((row * HS_STRIDE + kk + a_kof) << 1);
                asm volatile(
                    "ldmatrix.sync.aligned.m8n8.x4.shared.b16 {%0,%1,%2,%3}, [%4];"
                    : "=r"(af[mi][0]), "=r"(af[mi][1]),
                      "=r"(af[mi][2]), "=r"(af[mi][3])
                    : "r"(addr));
            }
#pragma unroll
            for (int p = 0; p < 2; p++) {
                int n = wn * 32 + p * 16 + b_row;
                uint32_t addr = bs_base + ((n * HS_STRIDE + kk + b_kof) << 1);
                uint32_t r0, r1, r2, r3;
                asm volatile(
                    "ldmatrix.sync.aligned.m8n8.x4.shared.b16 {%0,%1,%2,%3}, [%4];"
                    : "=r"(r0), "=r"(r1), "=r"(r2), "=r"(r3)
                    : "r"(addr));
                bf[2 * p][0] = r0;     bf[2 * p][1] = r1;      // n low 8
                bf[2 * p + 1][0] = r2; bf[2 * p + 1][1] = r3;  // n high 8
            }
#pragma unroll
            for (int mi = 0; mi < 4; mi++)
#pragma unroll
                for (int ni = 0; ni < 4; ni++)
                    mma_f16(acc[mi][ni], af[mi], bf[ni]);
        }
        // stage written below was last read at kt-1; top-of-loop barrier ordered it
        if (kt + 2 < G1_KT) load_stage((kt + 2) % STAGES, (kt + 2) * G1_BK);
        asm volatile("cp.async.commit_group;");
    }

    // epilogue: scale by dinv[row], write p1h (half2 stores)
#pragma unroll
    for (int mi = 0; mi < 4; mi++) {
        int r0 = brow + wm * 64 + mi * 16 + (lane >> 2);
        int r1 = r0 + 8;
        float dv0 = (r0 < N) ? g_dinv[r0] : 0.f;
        float dv1 = (r1 < N) ? g_dinv[r1] : 0.f;
#pragma unroll
        for (int ni = 0; ni < 4; ni++) {
            int c = bcol + wn * 32 + ni * 8 + (lane & 3) * 2;
            if (r0 < N) {
                __half2 v = __floats2half2_rn(dv0 * acc[mi][ni][0],
                                              dv0 * acc[mi][ni][1]);
                *(__half2*)&g_p1h[(long)r0 * M + c] = v;
            }
            if (r1 < N) {
                __half2 v = __floats2half2_rn(dv1 * acc[mi][ni][2],
                                              dv1 * acc[mi][ni][3]);
                *(__half2*)&g_p1h[(long)r1 * M + c] = v;
            }
        }
    }
}

// ---------------------------------------------------------------------------
// gather1 (F=256, fp16 src): a1[d] = relu(dinv[d]*(p1[d]+sum p1[s]) + b1)
// 32 threads per node (uint4 = 8 halves each), 8 nodes per 256-thread block
// ---------------------------------------------------------------------------
__global__ void __launch_bounds__(256) gather1_kernel(const float* __restrict__ b1, int N) {
    int tid = threadIdx.x;
    int d = blockIdx.x * 8 + (tid >> 5);
    int lane = tid & 31;
    if (d >= N) return;

    const uint4* p1v = (const uint4*)g_p1h;    // 8 halves per uint4; 32/row
    long rowbase = (long)d * 32;

    int start = g_rowstart[d];
    int deg = g_deg[d];

    float acc0[8], acc1[8];
    {
        uint4 v = p1v[rowbase + lane];
        const __half2* h = (const __half2*)&v;
#pragma unroll
        for (int i = 0; i < 4; i++) {
            float2 f = __half22float2(h[i]);
            acc0[2 * i] = f.x; acc0[2 * i + 1] = f.y;
            acc1[2 * i] = 0.f; acc1[2 * i + 1] = 0.f;
        }
    }

    int j = 0;
    for (; j + 1 < deg; j += 2) {
        int s0 = __ldg(&g_csrc[start + j]);
        int s1 = __ldg(&g_csrc[start + j + 1]);
        uint4 v0 = p1v[(long)s0 * 32 + lane];
        uint4 v1 = p1v[(long)s1 * 32 + lane];
        h8add(acc0, v0);
        h8add(acc1, v1);
    }
    if (j < deg) {
        int s0 = __ldg(&g_csrc[start + j]);
        h8add(acc0, p1v[(long)s0 * 32 + lane]);
    }

    float dv = g_dinv[d];
    float4 ba = *(const float4*)&b1[lane * 8];
    float4 bb = *(const float4*)&b1[lane * 8 + 4];
    float o[8];
#pragma unroll
    for (int i = 0; i < 8; i++) o[i] = dv * (acc0[i] + acc1[i]);
    o[0] += ba.x; o[1] += ba.y; o[2] += ba.z; o[3] += ba.w;
    o[4] += bb.x; o[5] += bb.y; o[6] += bb.z; o[7] += bb.w;
#pragma unroll
    for (int i = 0; i < 8; i++) o[i] = o[i] > 0.f ? o[i] : 0.f;

    float* op = &g_a1[(long)d * H1 + lane * 8];
    *(float4*)&op[0] = make_float4(o[0], o[1], o[2], o[3]);
    *(float4*)&op[4] = make_float4(o[4], o[5], o[6], o[7]);
}

// ---------------------------------------------------------------------------
// GEMM2: one thread per node. p2[n] = dinv[n] * (a1[n] @ W2)
// ---------------------------------------------------------------------------
__global__ void __launch_bounds__(256) gemm2_kernel(const float* __restrict__ W, int N) {
    __shared__ float Ws[H1 * H2];      // 16 KB
    int tid = threadIdx.x;
    for (int i = tid; i < H1 * H2; i += 256) Ws[i] = W[i];
    __syncthreads();

    int n = blockIdx.x * 256 + tid;
    if (n >= N) return;

    float acc[H2];
#pragma unroll
    for (int m = 0; m < H2; m++) acc[m] = 0.f;

    const float4* arow = (const float4*)(g_a1 + (long)n * H1);
    for (int k4 = 0; k4 < H1 / 4; k4++) {
        float4 a = arow[k4];
        const float* wk = &Ws[k4 * 4 * H2];
#pragma unroll
        for (int m = 0; m < H2; m++) {
            acc[m] += a.x * wk[m] + a.y * wk[H2 + m] +
                      a.z * wk[2 * H2 + m] + a.w * wk[3 * H2 + m];
        }
    }

    float dv = g_dinv[n];
    float* op = &g_p2[(long)n * H2];
#pragma unroll
    for (int m4 = 0; m4 < 4; m4++) {
        float4 v = make_float4(dv * acc[m4 * 4 + 0], dv * acc[m4 * 4 + 1],
                               dv * acc[m4 * 4 + 2], dv * acc[m4 * 4 + 3]);
        *(float4*)&op[m4 * 4] = v;
    }
}

// ---------------------------------------------------------------------------
// gather2 (F=16, float4): p3[d] = dinv[d]*relu(dinv[d]*(p2[d]+sum p2[s]) + b2)
// ---------------------------------------------------------------------------
__global__ void __launch_bounds__(256) gather2_kernel(const float* __restrict__ b2, int N) {
    int tid = threadIdx.x;
    int d = blockIdx.x * 64 + (tid >> 2);
    int f4 = tid & 3;
    if (d >= N) return;

    const float4* p2v = (const float4*)g_p2;
    int start = g_rowstart[d];
    int deg = g_deg[d];

    float4 acc0 = p2v[(long)d * 4 + f4];
    float4 acc1 = make_float4(0.f, 0.f, 0.f, 0.f);
    int j = 0;
    for (; j + 1 < deg; j += 2) {
        int s0 = __ldg(&g_csrc[start + j]);
        int s1 = __ldg(&g_csrc[start + j + 1]);
        acc0 = f4add(acc0, p2v[(long)s0 * 4 + f4]);
        acc1 = f4add(acc1, p2v[(long)s1 * 4 + f4]);
    }
    if (j < deg) {
        int s0 = __ldg(&g_csrc[start + j]);
        acc0 = f4add(acc0, p2v[(long)s0 * 4 + f4]);
    }

    float dv = g_dinv[d];
    float4 bb = ((const float4*)b2)[f4];
    float4 v = make_float4(dv * (acc0.x + acc1.x) + bb.x,
                           dv * (acc0.y + acc1.y) + bb.y,
                           dv * (acc0.z + acc1.z) + bb.z,
                           dv * (acc0.w + acc1.w) + bb.w);
    v.x = dv * (v.x > 0.f ? v.x : 0.f);
    v.y = dv * (v.y > 0.f ? v.y : 0.f);
    v.z = dv * (v.z > 0.f ? v.z : 0.f);
    v.w = dv * (v.w > 0.f ? v.w : 0.f);
    ((float4*)g_p3)[(long)d * 4 + f4] = v;
}

// ---------------------------------------------------------------------------
// gather3 (F=16, float4): a3[d] = dinv[d]*(p3[d]+sum p3[s])
// ---------------------------------------------------------------------------
__global__ void __launch_bounds__(256) gather3_kernel(int N) {
    int tid = threadIdx.x;
    int d = blockIdx.x * 64 + (tid >> 2);
    int f4 = tid & 3;
    if (d >= N) return;

    const float4* p3v = (const float4*)g_p3;
    int start = g_rowstart[d];
    int deg = g_deg[d];

    float4 acc0 = p3v[(long)d * 4 + f4];
    float4 acc1 = make_float4(0.f, 0.f, 0.f, 0.f);
    int j = 0;
    for (; j + 1 < deg; j += 2) {
        int s0 = __ldg(&g_csrc[start + j]);
        int s1 = __ldg(&g_csrc[start + j + 1]);
        acc0 = f4add(acc0, p3v[(long)s0 * 4 + f4]);
        acc1 = f4add(acc1, p3v[(long)s1 * 4 + f4]);
    }
    if (j < deg) {
        int s0 = __ldg(&g_csrc[start + j]);
        acc0 = f4add(acc0, p3v[(long)s0 * 4 + f4]);
    }

    float dv = g_dinv[d];
    float4 v = make_float4(dv * (acc0.x + acc1.x), dv * (acc0.y + acc1.y),
                           dv * (acc0.z + acc1.z), dv * (acc0.w + acc1.w));
    ((float4*)g_a3)[(long)d * 4 + f4] = v;
}

// ---------------------------------------------------------------------------
// final: o = g_a3 @ W3 + b3 ; log_softmax ; one thread per node
// ---------------------------------------------------------------------------
__global__ void final_kernel(const float* __restrict__ W3,
                             const float* __restrict__ b3,
                             float* __restrict__ out, int N) {
    __shared__ float Ws[H2 * F_OUT];
    __shared__ float bs[F_OUT];
    int tid = threadIdx.x;
    for (int i = tid; i < H2 * F_OUT; i += blockDim.x) Ws[i] = W3[i];
    if (tid < F_OUT) bs[tid] = b3[tid];
    __syncthreads();

    int n = blockIdx.x * blockDim.x + tid;
    if (n >= N) return;

    float a[H2];
    const float4* ap = (const float4*)(g_a3 + (long)n * H2);
#pragma unroll
    for (int i = 0; i < 4; i++) {
        float4 v = ap[i];
        a[i * 4 + 0] = v.x; a[i * 4 + 1] = v.y;
        a[i * 4 + 2] = v.z; a[i * 4 + 3] = v.w;
    }

    float o[F_OUT];
#pragma unroll
    for (int m = 0; m < F_OUT; m++) {
        float acc = bs[m];
#pragma unroll
        for (int k = 0; k < H2; k++) acc += a[k] * Ws[k * F_OUT + m];
        o[m] = acc;
    }

    float mx = o[0];
#pragma unroll
    for (int m = 1; m < F_OUT; m++) mx = fmaxf(mx, o[m]);
    float sum = 0.f;
#pragma unroll
    for (int m = 0; m < F_OUT; m++) sum += __expf(o[m] - mx);
    float lse = mx + __logf(sum);

    float* op = out + (long)n * F_OUT;
#pragma unroll
    for (int m = 0; m < F_OUT; m++) op[m] = o[m] - lse;
}

// ---------------------------------------------------------------------------
// host launcher — kernel launches only
// ---------------------------------------------------------------------------
extern "C" void kernel_launch(void* const* d_in, const int* in_sizes, int n_in,
                              void* d_out, int out_size) {
    const float* x  = (const float*)d_in[0];
    const int*   ei = (const int*)d_in[1];      // int64 delivered as int32
    const float* W1 = (const float*)d_in[2];
    const float* b1 = (const float*)d_in[3];
    const float* W2 = (const float*)d_in[4];
    const float* b2 = (const float*)d_in[5];
    const float* W3 = (const float*)d_in[6];
    const float* b3 = (const float*)d_in[7];
    float* out = (float*)d_out;

    int N = in_sizes[0] / F_IN;
    int E = in_sizes[1] / 2;
    int nblk = (N + SCAN_B - 1) / SCAN_B;
    long total8 = (long)N * F_IN / 8;

    // degree + dinv + fp16 conversions
    zero_deg_kernel<<<(N + 255) / 256, 256>>>(N);
    count_deg_kernel<<<(E + 255) / 256, 256>>>(ei, E, N);
    dinv_kernel<<<(N + 255) / 256, 256>>>(N);
    convert_w1t_kernel<<<(H1 * F_IN + 255) / 256, 256>>>(W1);
    convert_x_kernel<<<(int)((total8 + 255) / 256), 256>>>(x, total8);

    // layer 1 GEMM (fp16 MMA + cp.async + ldmatrix, dinv fused, fp16 out)
    {
        dim3 grid(H1 / G1_BN, (N + G1_BM - 1) / G1_BM);
        gemm1_kernel<<<grid, 256>>>(N);
    }

    // CSR build
    scan_partial_kernel<<<nblk, SCAN_B>>>(N);
    scan_bsum_kernel<<<1, SCAN_B>>>(nblk);
    scan_add_kernel<<<(N + 255) / 256, 256>>>(N);
    csr_fill_kernel<<<(E + 255) / 256, 256>>>(ei, E, N);

    // layer 1 aggregation (+bias/relu), fp16 gather
    gather1_kernel<<<(N + 7) / 8, 256>>>(b1, N);

    // layer 2
    gemm2_kernel<<<(N + 255) / 256, 256>>>(W2, N);
    gather2_kernel<<<(N + 63) / 64, 256>>>(b2, N);

    // layer 3 aggregation + head
    gather3_kernel<<<(N + 63) / 64, 256>>>(N);
    final_kernel<<<(N + 255) / 256, 256>>>(W3, b3, out, N);
}

// round 13
// speedup vs baseline: 2.0522x; 1.1183x over previous
#include <cuda_runtime.h>
#include <cuda_fp16.h>
#include <math.h>
#include <stdint.h>

// Problem constants (fixed for this problem instance)
#define NMAX   50000
#define EMAX   800000
#define F_IN   512
#define H1     256
#define H2     16
#define F_OUT  40

#define SCAN_B 256

// Scratch (static device arrays; no allocation allowed)
__device__ __half g_xh[NMAX * F_IN];  // x in fp16
__device__ __half g_w1t[H1 * F_IN];   // W1 transposed [m][k], fp16
__device__ __half g_p1h[NMAX * H1];   // dinv ⊙ (x @ W1), fp16
__device__ __half g_a1h[NMAX * H1];   // relu(Ahat h1 + b1), fp16
__device__ float g_p2[NMAX * H2];     // dinv ⊙ (a1 @ W2)
__device__ float g_p3[NMAX * H2];     // dinv ⊙ relu(Ahat h2 + b2)
__device__ float g_a3[NMAX * H2];     // Ahat r2
__device__ int   g_deg[NMAX];
__device__ int   g_rowstart[NMAX];
__device__ int   g_cursor[NMAX];
__device__ int   g_csrc[EMAX];
__device__ int   g_bsum[SCAN_B];
__device__ float g_dinv[NMAX];

__device__ __forceinline__ float4 f4add(float4 a, float4 b) {
    return make_float4(a.x + b.x, a.y + b.y, a.z + b.z, a.w + b.w);
}

__device__ __forceinline__ void h8add(float acc[8], uint4 v) {
    const __half2* h = (const __half2*)&v;
#pragma unroll
    for (int i = 0; i < 4; i++) {
        float2 f = __half22float2(h[i]);
        acc[2 * i]     += f.x;
        acc[2 * i + 1] += f.y;
    }
}

__device__ __forceinline__ void h8unpack(float f[8], uint4 v) {
    const __half2* h = (const __half2*)&v;
#pragma unroll
    for (int i = 0; i < 4; i++) {
        float2 t = __half22float2(h[i]);
        f[2 * i] = t.x;
        f[2 * i + 1] = t.y;
    }
}

// ---------------------------------------------------------------------------
// conversions
// ---------------------------------------------------------------------------
__global__ void convert_x_kernel(const float* __restrict__ x, long total8) {
    long i = (long)blockIdx.x * blockDim.x + threadIdx.x;
    if (i < total8) {
        float4 a = ((const float4*)x)[2 * i];
        float4 b = ((const float4*)x)[2 * i + 1];
        uint4 v;
        ((__half2*)&v)[0] = __floats2half2_rn(a.x, a.y);
        ((__half2*)&v)[1] = __floats2half2_rn(a.z, a.w);
        ((__half2*)&v)[2] = __floats2half2_rn(b.x, b.y);
        ((__half2*)&v)[3] = __floats2half2_rn(b.z, b.w);
        ((uint4*)g_xh)[i] = v;
    }
}

__global__ void convert_w1t_kernel(const float* __restrict__ W1) {
    int i = blockIdx.x * blockDim.x + threadIdx.x;   // over H1*F_IN
    if (i < H1 * F_IN) {
        int m = i >> 9;          // /512
        int k = i & 511;
        g_w1t[i] = __float2half_rn(W1[k * H1 + m]);
    }
}

// ---------------------------------------------------------------------------
// degree / dinv / scan / CSR fill
// ---------------------------------------------------------------------------
__global__ void zero_deg_kernel(int N) {
    int i = blockIdx.x * blockDim.x + threadIdx.x;
    if (i < N) g_deg[i] = 0;
}

__global__ void count_deg_kernel(const int* __restrict__ ei, int E, int N) {
    int e = blockIdx.x * blockDim.x + threadIdx.x;
    if (e < E) {
        int d = ei[E + e];
        if ((unsigned)d < (unsigned)N) atomicAdd(&g_deg[d], 1);
    }
}

__global__ void dinv_kernel(int N) {
    int i = blockIdx.x * blockDim.x + threadIdx.x;
    if (i < N) g_dinv[i] = rsqrtf((float)(g_deg[i] + 1));   // +1 self-loop
}

__global__ void scan_partial_kernel(int N) {
    __shared__ int sd[SCAN_B];
    int t = threadIdx.x, b = blockIdx.x;
    int i = b * SCAN_B + t;
    int v = (i < N) ? g_deg[i] : 0;
    sd[t] = v;
    __syncthreads();
#pragma unroll
    for (int off = 1; off < SCAN_B; off <<= 1) {
        int x = (t >= off) ? sd[t - off] : 0;
        __syncthreads();
        sd[t] += x;
        __syncthreads();
    }
    if (i < N) g_rowstart[i] = sd[t] - v;       // exclusive
    if (t == SCAN_B - 1) g_bsum[b] = sd[t];
}

__global__ void scan_bsum_kernel(int nblk) {
    __shared__ int sd[SCAN_B];
    int t = threadIdx.x;
    int v = (t < nblk) ? g_bsum[t] : 0;
    sd[t] = v;
    __syncthreads();
#pragma unroll
    for (int off = 1; off < SCAN_B; off <<= 1) {
        int x = (t >= off) ? sd[t - off] : 0;
        __syncthreads();
        sd[t] += x;
        __syncthreads();
    }
    if (t < nblk) g_bsum[t] = sd[t] - v;
}

__global__ void scan_add_kernel(int N) {
    int i = blockIdx.x * blockDim.x + threadIdx.x;
    if (i < N) {
        int r = g_rowstart[i] + g_bsum[i / SCAN_B];
        g_rowstart[i] = r;
        g_cursor[i] = r;
    }
}

__global__ void csr_fill_kernel(const int* __restrict__ ei, int E, int N) {
    int e = blockIdx.x * blockDim.x + threadIdx.x;
    if (e < E) {
        int s = ei[e];
        int d = ei[E + e];
        if ((unsigned)s < (unsigned)N && (unsigned)d < (unsigned)N) {
            int pos = atomicAdd(&g_cursor[d], 1);
            g_csrc[pos] = s;
        }
    }
}

// ---------------------------------------------------------------------------
// GEMM1 (fp16 tensor cores, mma.m16n8k16, fp32 accum, cp.async 3-stage,
// ldmatrix for A and B): g_p1h = dinv ⊙ (xh @ W1)
// ---------------------------------------------------------------------------
#define G1_BM 128
#define G1_BN 128
#define G1_BK 32
#define G1_KT (F_IN / G1_BK)   // 16 k-tiles
#define STAGES 3
#define HS_STRIDE 40           // halves; 80B rows, conflict-free ldmatrix

__device__ __forceinline__ void mma_f16(float c[4], const uint32_t a[4],
                                        const uint32_t b[2]) {
    asm volatile(
        "mma.sync.aligned.m16n8k16.row.col.f32.f16.f16.f32 "
        "{%0,%1,%2,%3}, {%4,%5,%6,%7}, {%8,%9}, {%0,%1,%2,%3};"
        : "+f"(c[0]), "+f"(c[1]), "+f"(c[2]), "+f"(c[3])
        : "r"(a[0]), "r"(a[1]), "r"(a[2]), "r"(a[3]), "r"(b[0]), "r"(b[1]));
}

__device__ __forceinline__ void cp_async16(uint32_t smem_dst, const void* gsrc,
                                           int src_bytes) {
    asm volatile("cp.async.ca.shared.global [%0], [%1], 16, %2;"
                 :: "r"(smem_dst), "l"(gsrc), "r"(src_bytes));
}

__global__ void __launch_bounds__(256) gemm1_kernel(int N) {
    const int M = H1;
    __shared__ __half As[STAGES][G1_BM * HS_STRIDE];   // 30 KB
    __shared__ __half Bs[STAGES][G1_BN * HS_STRIDE];   // 30 KB

    int tid = threadIdx.x;
    int lane = tid & 31;
    int w = tid >> 5;
    int wm = w >> 2;
    int wn = w & 3;
    int brow = blockIdx.y * G1_BM;
    int bcol = blockIdx.x * G1_BN;

    int ldrow = tid >> 1;
    int ldoff = (tid & 1) * 16;

    int gr = brow + ldrow;
    int a_ok = (gr < N) ? 16 : 0;
    const __half* a_src0 = &g_xh[(long)gr * F_IN + ldoff];
    const __half* b_src0 = &g_w1t[(long)(bcol + ldrow) * F_IN + ldoff];

    auto load_stage = [&](int st, int k0) {
        uint32_t ad = (uint32_t)__cvta_generic_to_shared(
            &As[st][ldrow * HS_STRIDE + ldoff]);
        cp_async16(ad, a_src0 + k0, a_ok);
        cp_async16(ad + 16, a_src0 + k0 + 8, a_ok);
        uint32_t bd = (uint32_t)__cvta_generic_to_shared(
            &Bs[st][ldrow * HS_STRIDE + ldoff]);
        cp_async16(bd, b_src0 + k0, 16);
        cp_async16(bd + 16, b_src0 + k0 + 8, 16);
    };

    int lm_m = lane >> 3;
    int a_row = ((lm_m & 1) << 3) + (lane & 7);
    int a_kof = (lm_m >> 1) << 3;
    int b_nof = ((lane >> 4) & 1) << 3;
    int b_row = b_nof + (lane & 7);
    int b_kof = ((lane >> 3) & 1) << 3;

    float acc[4][4][4];
#pragma unroll
    for (int mi = 0; mi < 4; mi++)
#pragma unroll
        for (int ni = 0; ni < 4; ni++)
#pragma unroll
            for (int q = 0; q < 4; q++) acc[mi][ni][q] = 0.f;

    load_stage(0, 0);
    asm volatile("cp.async.commit_group;");
    load_stage(1, G1_BK);
    asm volatile("cp.async.commit_group;");

    for (int kt = 0; kt < G1_KT; kt++) {
        asm volatile("cp.async.wait_group 1;");
        __syncthreads();

        int buf = kt % STAGES;
        uint32_t as_base = (uint32_t)__cvta_generic_to_shared(&As[buf][0]);
        uint32_t bs_base = (uint32_t)__cvta_generic_to_shared(&Bs[buf][0]);
#pragma unroll
        for (int ks = 0; ks < 2; ks++) {
            int kk = ks * 16;
            uint32_t af[4][4], bf[4][2];
#pragma unroll
            for (int mi = 0; mi < 4; mi++) {
                int row = wm * 64 + mi * 16 + a_row;
                uint32_t addr = as_base + ((row * HS_STRIDE + kk + a_kof) << 1);
                asm volatile(
                    "ldmatrix.sync.aligned.m8n8.x4.shared.b16 {%0,%1,%2,%3}, [%4];"
                    : "=r"(af[mi][0]), "=r"(af[mi][1]),
                      "=r"(af[mi][2]), "=r"(af[mi][3])
                    : "r"(addr));
            }
#pragma unroll
            for (int p = 0; p < 2; p++) {
                int n = wn * 32 + p * 16 + b_row;
                uint32_t addr = bs_base + ((n * HS_STRIDE + kk + b_kof) << 1);
                uint32_t r0, r1, r2, r3;
                asm volatile(
                    "ldmatrix.sync.aligned.m8n8.x4.shared.b16 {%0,%1,%2,%3}, [%4];"
                    : "=r"(r0), "=r"(r1), "=r"(r2), "=r"(r3)
                    : "r"(addr));
                bf[2 * p][0] = r0;     bf[2 * p][1] = r1;
                bf[2 * p + 1][0] = r2; bf[2 * p + 1][1] = r3;
            }
#pragma unroll
            for (int mi = 0; mi < 4; mi++)
#pragma unroll
                for (int ni = 0; ni < 4; ni++)
                    mma_f16(acc[mi][ni], af[mi], bf[ni]);
        }
        if (kt + 2 < G1_KT) load_stage((kt + 2) % STAGES, (kt + 2) * G1_BK);
        asm volatile("cp.async.commit_group;");
    }

#pragma unroll
    for (int mi = 0; mi < 4; mi++) {
        int r0 = brow + wm * 64 + mi * 16 + (lane >> 2);
        int r1 = r0 + 8;
        float dv0 = (r0 < N) ? g_dinv[r0] : 0.f;
        float dv1 = (r1 < N) ? g_dinv[r1] : 0.f;
#pragma unroll
        for (int ni = 0; ni < 4; ni++) {
            int c = bcol + wn * 32 + ni * 8 + (lane & 3) * 2;
            if (r0 < N) {
                __half2 v = __floats2half2_rn(dv0 * acc[mi][ni][0],
                                              dv0 * acc[mi][ni][1]);
                *(__half2*)&g_p1h[(long)r0 * M + c] = v;
            }
            if (r1 < N) {
                __half2 v = __floats2half2_rn(dv1 * acc[mi][ni][2],
                                              dv1 * acc[mi][ni][3]);
                *(__half2*)&g_p1h[(long)r1 * M + c] = v;
            }
        }
    }
}

// ---------------------------------------------------------------------------
// gather1 (F=256, fp16 src AND dst): a1h[d] = relu(dinv[d]*(p1[d]+sum)+b1)
// 32 threads per node (uint4 = 8 halves each), 8 nodes per 256-thread block
// ---------------------------------------------------------------------------
__global__ void __launch_bounds__(256) gather1_kernel(const float* __restrict__ b1, int N) {
    int tid = threadIdx.x;
    int d = blockIdx.x * 8 + (tid >> 5);
    int lane = tid & 31;
    if (d >= N) return;

    const uint4* p1v = (const uint4*)g_p1h;
    long rowbase = (long)d * 32;

    int start = g_rowstart[d];
    int deg = g_deg[d];

    float acc0[8], acc1[8];
    {
        uint4 v = p1v[rowbase + lane];
        const __half2* h = (const __half2*)&v;
#pragma unroll
        for (int i = 0; i < 4; i++) {
            float2 f = __half22float2(h[i]);
            acc0[2 * i] = f.x; acc0[2 * i + 1] = f.y;
            acc1[2 * i] = 0.f; acc1[2 * i + 1] = 0.f;
        }
    }

    int j = 0;
    for (; j + 1 < deg; j += 2) {
        int s0 = __ldg(&g_csrc[start + j]);
        int s1 = __ldg(&g_csrc[start + j + 1]);
        uint4 v0 = p1v[(long)s0 * 32 + lane];
        uint4 v1 = p1v[(long)s1 * 32 + lane];
        h8add(acc0, v0);
        h8add(acc1, v1);
    }
    if (j < deg) {
        int s0 = __ldg(&g_csrc[start + j]);
        h8add(acc0, p1v[(long)s0 * 32 + lane]);
    }

    float dv = g_dinv[d];
    float4 ba = *(const float4*)&b1[lane * 8];
    float4 bb = *(const float4*)&b1[lane * 8 + 4];
    float o[8];
#pragma unroll
    for (int i = 0; i < 8; i++) o[i] = dv * (acc0[i] + acc1[i]);
    o[0] += ba.x; o[1] += ba.y; o[2] += ba.z; o[3] += ba.w;
    o[4] += bb.x; o[5] += bb.y; o[6] += bb.z; o[7] += bb.w;
#pragma unroll
    for (int i = 0; i < 8; i++) o[i] = o[i] > 0.f ? o[i] : 0.f;

    uint4 vout;
    ((__half2*)&vout)[0] = __floats2half2_rn(o[0], o[1]);
    ((__half2*)&vout)[1] = __floats2half2_rn(o[2], o[3]);
    ((__half2*)&vout)[2] = __floats2half2_rn(o[4], o[5]);
    ((__half2*)&vout)[3] = __floats2half2_rn(o[6], o[7]);
    ((uint4*)g_a1h)[rowbase + lane] = vout;
}

// ---------------------------------------------------------------------------
// GEMM2: one thread per node. p2[n] = dinv[n] * (a1h[n] @ W2), fp16 input
// ---------------------------------------------------------------------------
__global__ void __launch_bounds__(256) gemm2_kernel(const float* __restrict__ W, int N) {
    __shared__ float Ws[H1 * H2];      // 16 KB
    int tid = threadIdx.x;
    for (int i = tid; i < H1 * H2; i += 256) Ws[i] = W[i];
    __syncthreads();

    int n = blockIdx.x * 256 + tid;
    if (n >= N) return;

    float acc[H2];
#pragma unroll
    for (int m = 0; m < H2; m++) acc[m] = 0.f;

    const uint4* arow = (const uint4*)(g_a1h + (long)n * H1);  // 32 uint4/row
    for (int k8 = 0; k8 < H1 / 8; k8++) {
        float f[8];
        h8unpack(f, arow[k8]);
        const float* wk = &Ws[k8 * 8 * H2];
#pragma unroll
        for (int m = 0; m < H2; m++) {
            float s = f[0] * wk[m]          + f[1] * wk[H2 + m] +
                      f[2] * wk[2 * H2 + m] + f[3] * wk[3 * H2 + m] +
                      f[4] * wk[4 * H2 + m] + f[5] * wk[5 * H2 + m] +
                      f[6] * wk[6 * H2 + m] + f[7] * wk[7 * H2 + m];
            acc[m] += s;
        }
    }

    float dv = g_dinv[n];
    float* op = &g_p2[(long)n * H2];
#pragma unroll
    for (int m4 = 0; m4 < 4; m4++) {
        float4 v = make_float4(dv * acc[m4 * 4 + 0], dv * acc[m4 * 4 + 1],
                               dv * acc[m4 * 4 + 2], dv * acc[m4 * 4 + 3]);
        *(float4*)&op[m4 * 4] = v;
    }
}

// ---------------------------------------------------------------------------
// gather2 (F=16, float4): p3[d] = dinv[d]*relu(dinv[d]*(p2[d]+sum p2[s]) + b2)
// ---------------------------------------------------------------------------
__global__ void __launch_bounds__(256) gather2_kernel(const float* __restrict__ b2, int N) {
    int tid = threadIdx.x;
    int d = blockIdx.x * 64 + (tid >> 2);
    int f4 = tid & 3;
    if (d >= N) return;

    const float4* p2v = (const float4*)g_p2;
    int start = g_rowstart[d];
    int deg = g_deg[d];

    float4 acc0 = p2v[(long)d * 4 + f4];
    float4 acc1 = make_float4(0.f, 0.f, 0.f, 0.f);
    int j = 0;
    for (; j + 1 < deg; j += 2) {
        int s0 = __ldg(&g_csrc[start + j]);
        int s1 = __ldg(&g_csrc[start + j + 1]);
        acc0 = f4add(acc0, p2v[(long)s0 * 4 + f4]);
        acc1 = f4add(acc1, p2v[(long)s1 * 4 + f4]);
    }
    if (j < deg) {
        int s0 = __ldg(&g_csrc[start + j]);
        acc0 = f4add(acc0, p2v[(long)s0 * 4 + f4]);
    }

    float dv = g_dinv[d];
    float4 bb = ((const float4*)b2)[f4];
    float4 v = make_float4(dv * (acc0.x + acc1.x) + bb.x,
                           dv * (acc0.y + acc1.y) + bb.y,
                           dv * (acc0.z + acc1.z) + bb.z,
                           dv * (acc0.w + acc1.w) + bb.w);
    v.x = dv * (v.x > 0.f ? v.x : 0.f);
    v.y = dv * (v.y > 0.f ? v.y : 0.f);
    v.z = dv * (v.z > 0.f ? v.z : 0.f);
    v.w = dv * (v.w > 0.f ? v.w : 0.f);
    ((float4*)g_p3)[(long)d * 4 + f4] = v;
}

// ---------------------------------------------------------------------------
// gather3 (F=16, float4): a3[d] = dinv[d]*(p3[d]+sum p3[s])
// ---------------------------------------------------------------------------
__global__ void __launch_bounds__(256) gather3_kernel(int N) {
    int tid = threadIdx.x;
    int d = blockIdx.x * 64 + (tid >> 2);
    int f4 = tid & 3;
    if (d >= N) return;

    const float4* p3v = (const float4*)g_p3;
    int start = g_rowstart[d];
    int deg = g_deg[d];

    float4 acc0 = p3v[(long)d * 4 + f4];
    float4 acc1 = make_float4(0.f, 0.f, 0.f, 0.f);
    int j = 0;
    for (; j + 1 < deg; j += 2) {
        int s0 = __ldg(&g_csrc[start + j]);
        int s1 = __ldg(&g_csrc[start + j + 1]);
        acc0 = f4add(acc0, p3v[(long)s0 * 4 + f4]);
        acc1 = f4add(acc1, p3v[(long)s1 * 4 + f4]);
    }
    if (j < deg) {
        int s0 = __ldg(&g_csrc[start + j]);
        acc0 = f4add(acc0, p3v[(long)s0 * 4 + f4]);
    }

    float dv = g_dinv[d];
    float4 v = make_float4(dv * (acc0.x + acc1.x), dv * (acc0.y + acc1.y),
                           dv * (acc0.z + acc1.z), dv * (acc0.w + acc1.w));
    ((float4*)g_a3)[(long)d * 4 + f4] = v;
}

// ---------------------------------------------------------------------------
// final: o = g_a3 @ W3 + b3 ; log_softmax ; one thread per node
// ---------------------------------------------------------------------------
__global__ void final_kernel(const float* __restrict__ W3,
                             const float* __restrict__ b3,
                             float* __restrict__ out, int N) {
    __shared__ float Ws[H2 * F_OUT];
    __shared__ float bs[F_OUT];
    int tid = threadIdx.x;
    for (int i = tid; i < H2 * F_OUT; i += blockDim.x) Ws[i] = W3[i];
    if (tid < F_OUT) bs[tid] = b3[tid];
    __syncthreads();

    int n = blockIdx.x * blockDim.x + tid;
    if (n >= N) return;

    float a[H2];
    const float4* ap = (const float4*)(g_a3 + (long)n * H2);
#pragma unroll
    for (int i = 0; i < 4; i++) {
        float4 v = ap[i];
        a[i * 4 + 0] = v.x; a[i * 4 + 1] = v.y;
        a[i * 4 + 2] = v.z; a[i * 4 + 3] = v.w;
    }

    float o[F_OUT];
#pragma unroll
    for (int m = 0; m < F_OUT; m++) {
        float acc = bs[m];
#pragma unroll
        for (int k = 0; k < H2; k++) acc += a[k] * Ws[k * F_OUT + m];
        o[m] = acc;
    }

    float mx = o[0];
#pragma unroll
    for (int m = 1; m < F_OUT; m++) mx = fmaxf(mx, o[m]);
    float sum = 0.f;
#pragma unroll
    for (int m = 0; m < F_OUT; m++) sum += __expf(o[m] - mx);
    float lse = mx + __logf(sum);

    float* op = out + (long)n * F_OUT;
#pragma unroll
    for (int m = 0; m < F_OUT; m++) op[m] = o[m] - lse;
}

// ---------------------------------------------------------------------------
// host launcher — kernel launches + event-forked side stream (capturable).
// Two independent chains run as parallel graph branches:
//   main:  zero → count → dinv → gemm1 → gather1 → gemm2 → ... → final
//   side:  converts (x, W1t)  |  CSR scan+fill (after count_deg)
// ---------------------------------------------------------------------------
extern "C" void kernel_launch(void* const* d_in, const int* in_sizes, int n_in,
                              void* d_out, int out_size) {
    const float* x  = (const float*)d_in[0];
    const int*   ei = (const int*)d_in[1];      // int64 delivered as int32
    const float* W1 = (const float*)d_in[2];
    const float* b1 = (const float*)d_in[3];
    const float* W2 = (const float*)d_in[4];
    const float* b2 = (const float*)d_in[5];
    const float* W3 = (const float*)d_in[6];
    const float* b3 = (const float*)d_in[7];
    float* out = (float*)d_out;

    int N = in_sizes[0] / F_IN;
    int E = in_sizes[1] / 2;
    int nblk = (N + SCAN_B - 1) / SCAN_B;
    long total8 = (long)N * F_IN / 8;

    // lazily created once; reused every call (no device-memory allocation,
    // identical work per call)
    static cudaStream_t s1 = nullptr;
    static cudaEvent_t e_start = nullptr, e_conv = nullptr,
                       e_deg = nullptr, e_csr = nullptr;
    if (s1 == nullptr) {
        cudaStreamCreateWithFlags(&s1, cudaStreamNonBlocking);
        cudaEventCreateWithFlags(&e_start, cudaEventDisableTiming);
        cudaEventCreateWithFlags(&e_conv, cudaEventDisableTiming);
        cudaEventCreateWithFlags(&e_deg, cudaEventDisableTiming);
        cudaEventCreateWithFlags(&e_csr, cudaEventDisableTiming);
    }

    // fork side stream from the (captured) main stream
    cudaEventRecord(e_start, 0);
    cudaStreamWaitEvent(s1, e_start, 0);

    // side: fp16 conversions (independent of everything)
    convert_w1t_kernel<<<(H1 * F_IN + 255) / 256, 256, 0, s1>>>(W1);
    convert_x_kernel<<<(int)((total8 + 255) / 256), 256, 0, s1>>>(x, total8);
    cudaEventRecord(e_conv, s1);

    // main: degree + dinv
    zero_deg_kernel<<<(N + 255) / 256, 256>>>(N);
    count_deg_kernel<<<(E + 255) / 256, 256>>>(ei, E, N);
    cudaEventRecord(e_deg, 0);
    dinv_kernel<<<(N + 255) / 256, 256>>>(N);

    // side: CSR build (needs g_deg complete)
    cudaStreamWaitEvent(s1, e_deg, 0);
    scan_partial_kernel<<<nblk, SCAN_B, 0, s1>>>(N);
    scan_bsum_kernel<<<1, SCAN_B, 0, s1>>>(nblk);
    scan_add_kernel<<<(N + 255) / 256, 256, 0, s1>>>(N);
    csr_fill_kernel<<<(E + 255) / 256, 256, 0, s1>>>(ei, E, N);
    cudaEventRecord(e_csr, s1);

    // main: gemm1 (needs converts + dinv)
    cudaStreamWaitEvent(0, e_conv, 0);
    {
        dim3 grid(H1 / G1_BN, (N + G1_BM - 1) / G1_BM);
        gemm1_kernel<<<grid, 256>>>(N);
    }

    // main: join CSR branch, then aggregation chain
    cudaStreamWaitEvent(0, e_csr, 0);
    gather1_kernel<<<(N + 7) / 8, 256>>>(b1, N);
    gemm2_kernel<<<(N + 255) / 256, 256>>>(W2, N);
    gather2_kernel<<<(N + 63) / 64, 256>>>(b2, N);
    gather3_kernel<<<(N + 63) / 64, 256>>>(N);
    final_kernel<<<(N + 255) / 256, 256>>>(W3, b3, out, N);
}